// round 4
// baseline (speedup 1.0000x reference)
#include <cuda_runtime.h>
#include <cuda_bf16.h>

#define NN 20000
#define EE 320000
#define IN_C 128
#define HID 64
#define OUT_C 32
#define NEG_SLOPE 0.2f

// ---------------- scratch (device globals; no allocation) ----------------
__device__ __align__(16) float g_h[NN * 256];   // GEMM output (max H*C = 256)
__device__ __align__(16) float g_f1[NN * 64];   // layer-1 node features
__device__ __align__(16) float g_f2[NN * 64];   // layer-2 node features
__device__ __align__(16) float g_as[NN * 4];    // alpha_src per node (max 4 heads)
__device__ __align__(16) float g_ad[NN * 4];    // alpha_dst per node
__device__ int   g_deg[NN];
__device__ int   g_rowptr[NN + 1];
__device__ int   g_cursor[NN];
__device__ int   g_col[EE + NN];                // CSR: src per incoming edge (incl. self loops)

// buffer selector: 0 = external pointer, 1 = g_f1, 2 = g_f2
__device__ __forceinline__ float* sel_buf(int sel, float* ext) {
    if (sel == 1) return g_f1;
    if (sel == 2) return g_f2;
    return ext;
}
__device__ __forceinline__ const float* sel_cbuf(int sel, const float* ext) {
    if (sel == 1) return g_f1;
    if (sel == 2) return g_f2;
    return ext;
}

// ---------------- CSR build ----------------
__global__ void deg_init() {
    int i = blockIdx.x * blockDim.x + threadIdx.x;
    if (i < NN) g_deg[i] = 1;  // self loop
}

__global__ void deg_hist(const int* __restrict__ ei) {
    int e = blockIdx.x * blockDim.x + threadIdx.x;
    if (e < EE) {
        int d = ei[EE + e];
        atomicAdd(&g_deg[d], 1);
    }
}

__global__ void scan_kernel() {
    __shared__ int warpsum[32];
    __shared__ int carry_s;
    int tid = threadIdx.x, lane = tid & 31, wid = tid >> 5;
    if (tid == 0) { carry_s = 0; g_rowptr[0] = 0; }
    __syncthreads();
    for (int base = 0; base < NN; base += 1024) {
        int i = base + tid;
        int v = (i < NN) ? g_deg[i] : 0;
        int x = v;
#pragma unroll
        for (int off = 1; off < 32; off <<= 1) {
            int t = __shfl_up_sync(0xffffffffu, x, off);
            if (lane >= off) x += t;
        }
        if (lane == 31) warpsum[wid] = x;
        __syncthreads();
        if (wid == 0) {
            int w = warpsum[lane];
#pragma unroll
            for (int off = 1; off < 32; off <<= 1) {
                int t = __shfl_up_sync(0xffffffffu, w, off);
                if (lane >= off) w += t;
            }
            warpsum[lane] = w;
        }
        __syncthreads();
        int prefix = (wid > 0 ? warpsum[wid - 1] : 0) + carry_s;
        int incl = prefix + x;
        if (i < NN) { g_rowptr[i + 1] = incl; g_cursor[i] = incl - v; }
        __syncthreads();
        if (tid == 0) carry_s += warpsum[31];
        __syncthreads();
    }
}

__global__ void scatter_kernel(const int* __restrict__ ei) {
    int id = blockIdx.x * blockDim.x + threadIdx.x;
    if (id >= EE + NN) return;
    int s, d;
    if (id < EE) { s = ei[id]; d = ei[EE + id]; }
    else { s = d = id - EE; }
    int pos = atomicAdd(&g_cursor[d], 1);
    g_col[pos] = s;
}

// ---------------- SGEMM: g_h[Nr,M] = A[Nr,K] @ B[K,M] ----------------
__global__ void sgemm(const float* __restrict__ Aext, int Asel,
                      const float* __restrict__ B, int Nr, int K, int M) {
    const float* A = sel_cbuf(Asel, Aext);
    float* C = g_h;
    __shared__ float As[64][68];
    __shared__ float Bs[64][68];
    int tid = threadIdx.x;
    int tx = tid & 15, ty = tid >> 4;
    int row0 = blockIdx.y * 64;
    int col0 = blockIdx.x * 64;
    float acc[4][4] = {};
    for (int kt = 0; kt < K; kt += 64) {
#pragma unroll
        for (int i = 0; i < 4; i++) {
            int lin = tid + i * 256;
            int r = lin >> 4;
            int k4 = (lin & 15) * 4;
            float4 v = make_float4(0.f, 0.f, 0.f, 0.f);
            if (row0 + r < Nr)
                v = *(const float4*)(A + (size_t)(row0 + r) * K + kt + k4);
            As[k4 + 0][r] = v.x; As[k4 + 1][r] = v.y;
            As[k4 + 2][r] = v.z; As[k4 + 3][r] = v.w;
        }
        if (col0 + 64 <= M) {
#pragma unroll
            for (int i = 0; i < 4; i++) {
                int lin = tid + i * 256;
                int kk = lin >> 4;
                int c4 = (lin & 15) * 4;
                float4 v = *(const float4*)(B + (size_t)(kt + kk) * M + col0 + c4);
                Bs[kk][c4 + 0] = v.x; Bs[kk][c4 + 1] = v.y;
                Bs[kk][c4 + 2] = v.z; Bs[kk][c4 + 3] = v.w;
            }
        } else {
#pragma unroll
            for (int i = 0; i < 4; i++) {
                int lin = tid + i * 256;
                int kk = lin >> 4;
                int c4 = (lin & 15) * 4;
#pragma unroll
                for (int j = 0; j < 4; j++) {
                    int c = c4 + j;
                    Bs[kk][c] = (col0 + c < M) ? B[(size_t)(kt + kk) * M + col0 + c] : 0.f;
                }
            }
        }
        __syncthreads();
#pragma unroll 8
        for (int kk = 0; kk < 64; kk++) {
            float4 a = *(const float4*)&As[kk][ty * 4];
            float4 b = *(const float4*)&Bs[kk][tx * 4];
            float av[4] = {a.x, a.y, a.z, a.w};
            float bv[4] = {b.x, b.y, b.z, b.w};
#pragma unroll
            for (int i = 0; i < 4; i++)
#pragma unroll
                for (int j = 0; j < 4; j++)
                    acc[i][j] = fmaf(av[i], bv[j], acc[i][j]);
        }
        __syncthreads();
    }
#pragma unroll
    for (int i = 0; i < 4; i++) {
        int r = row0 + ty * 4 + i;
        if (r >= Nr) continue;
#pragma unroll
        for (int j = 0; j < 4; j++) {
            int c = col0 + tx * 4 + j;
            if (c < M) C[(size_t)r * M + c] = acc[i][j];
        }
    }
}

// ---------------- alpha = einsum('nhc,hc->nh'), h = g_h ----------------
template <int H, int C>
__global__ void compute_alpha(const float* __restrict__ a_s, const float* __restrict__ a_d) {
    constexpr int HC = H * C;
    constexpr int SLOTS = HC / 32;
    int warp = (blockIdx.x * blockDim.x + threadIdx.x) >> 5;
    int lane = threadIdx.x & 31;
    if (warp >= NN) return;
    float ps[H], pd[H];
#pragma unroll
    for (int hh = 0; hh < H; hh++) { ps[hh] = 0.f; pd[hh] = 0.f; }
    const float* hr = g_h + (size_t)warp * HC;
#pragma unroll
    for (int k = 0; k < SLOTS; k++) {
        int flat = lane + 32 * k;
        float v = hr[flat];
        ps[(32 * k) / C] = fmaf(v, a_s[flat], ps[(32 * k) / C]);
        pd[(32 * k) / C] = fmaf(v, a_d[flat], pd[(32 * k) / C]);
    }
#pragma unroll
    for (int hh = 0; hh < H; hh++) {
#pragma unroll
        for (int off = 16; off > 0; off >>= 1) {
            ps[hh] += __shfl_xor_sync(0xffffffffu, ps[hh], off);
            pd[hh] += __shfl_xor_sync(0xffffffffu, pd[hh], off);
        }
    }
    if (lane == 0) {
#pragma unroll
        for (int hh = 0; hh < H; hh++) {
            g_as[warp * H + hh] = ps[hh];
            g_ad[warp * H + hh] = pd[hh];
        }
    }
}

// ---------------- GAT softmax-aggregate, one warp per dst node ----------------
__device__ __forceinline__ float leaky(float x) { return x > 0.f ? x : NEG_SLOPE * x; }

template <int H, int C, bool RELU>
__global__ void gat_aggregate(const float* __restrict__ bias, float* __restrict__ out_ext,
                              int out_sel) {
    constexpr int HC = H * C;
    constexpr int SLOTS = HC / 32;
    constexpr int CG = C / 32;
    const float* h = g_h;
    float* out = sel_buf(out_sel, out_ext);
    int warp = (blockIdx.x * blockDim.x + threadIdx.x) >> 5;
    int lane = threadIdx.x & 31;
    if (warp >= NN) return;
    int n = warp;
    int beg = g_rowptr[n], end = g_rowptr[n + 1];

    float ad[H];
    if (H == 4) {
        float4 a = ((const float4*)g_ad)[n];
        ad[0] = a.x;
        if (H > 1) { ad[1] = a.y; ad[2] = a.z; ad[3] = a.w; }
    } else {
        ad[0] = g_ad[n * H];
    }

    // pass 1: per-head max of edge logits
    float m[H];
#pragma unroll
    for (int hh = 0; hh < H; hh++) m[hh] = -1e30f;
    for (int j = beg + lane; j < end; j += 32) {
        int s = g_col[j];
        if (H == 4) {
            float4 a = ((const float4*)g_as)[s];
            float as4[4] = {a.x, a.y, a.z, a.w};
#pragma unroll
            for (int hh = 0; hh < 4; hh++)
                m[hh] = fmaxf(m[hh], leaky(as4[hh] + ad[hh]));
        } else {
            m[0] = fmaxf(m[0], leaky(g_as[s * H] + ad[0]));
        }
    }
#pragma unroll
    for (int hh = 0; hh < H; hh++)
#pragma unroll
        for (int off = 16; off > 0; off >>= 1)
            m[hh] = fmaxf(m[hh], __shfl_xor_sync(0xffffffffu, m[hh], off));

    // pass 2: exp-sum + message accumulation
    float acc[SLOTS];
#pragma unroll
    for (int k = 0; k < SLOTS; k++) acc[k] = 0.f;
    float ssum[H];
#pragma unroll
    for (int hh = 0; hh < H; hh++) ssum[hh] = 0.f;

    for (int base = beg; base < end; base += 32) {
        int cnt = min(32, end - base);
        int sj = 0;
        float p[H];
#pragma unroll
        for (int hh = 0; hh < H; hh++) p[hh] = 0.f;
        if (lane < cnt) {
            sj = g_col[base + lane];
            if (H == 4) {
                float4 a = ((const float4*)g_as)[sj];
                float as4[4] = {a.x, a.y, a.z, a.w};
#pragma unroll
                for (int hh = 0; hh < 4; hh++) {
                    p[hh] = __expf(leaky(as4[hh] + ad[hh]) - m[hh]);
                    ssum[hh] += p[hh];
                }
            } else {
                p[0] = __expf(leaky(g_as[sj * H] + ad[0]) - m[0]);
                ssum[0] += p[0];
            }
        }
        for (int t = 0; t < cnt; ++t) {
            int src = __shfl_sync(0xffffffffu, sj, t);
            float pb[H];
#pragma unroll
            for (int hh = 0; hh < H; hh++)
                pb[hh] = __shfl_sync(0xffffffffu, p[hh], t);
            const float* hrow = h + (size_t)src * HC;
#pragma unroll
            for (int k = 0; k < SLOTS; k++)
                acc[k] = fmaf(pb[(32 * k) / C], hrow[lane + 32 * k], acc[k]);
        }
    }
#pragma unroll
    for (int hh = 0; hh < H; hh++)
#pragma unroll
        for (int off = 16; off > 0; off >>= 1)
            ssum[hh] += __shfl_xor_sync(0xffffffffu, ssum[hh], off);

    float inv[H];
#pragma unroll
    for (int hh = 0; hh < H; hh++) inv[hh] = 1.f / (ssum[hh] + 1e-16f);

#pragma unroll
    for (int g = 0; g < CG; g++) {
        int c = lane + 32 * g;
        float v = 0.f;
#pragma unroll
        for (int hh = 0; hh < H; hh++) v += acc[g + CG * hh] * inv[hh];
        v = v * (1.0f / H) + bias[c];
        if (RELU) v = fmaxf(v, 0.f);
        out[(size_t)n * C + c] = v;
    }
}

// ---------------- epilogue: z_mean, z_var ----------------
__global__ void epilogue(const float* __restrict__ z, const float* __restrict__ Wm,
                         const float* __restrict__ bm, const float* __restrict__ Wv,
                         const float* __restrict__ bv, float* __restrict__ outm,
                         float* __restrict__ outv) {
    __shared__ float sWm[1024], sWv[1024], sbm[32], sbv[32];
    int tid = threadIdx.x;
    for (int i = tid; i < 1024; i += blockDim.x) { sWm[i] = Wm[i]; sWv[i] = Wv[i]; }
    if (tid < 32) { sbm[tid] = bm[tid]; sbv[tid] = bv[tid]; }
    __syncthreads();
    int warp = (blockIdx.x * blockDim.x + tid) >> 5;
    int lane = tid & 31;
    if (warp >= NN) return;
    float zc = z[(size_t)warp * 32 + lane];
    float am = 0.f, av = 0.f;
#pragma unroll
    for (int k = 0; k < 32; k++) {
        float zk = __shfl_sync(0xffffffffu, zc, k);
        am = fmaf(zk, sWm[k * 32 + lane], am);
        av = fmaf(zk, sWv[k * 32 + lane], av);
    }
    outm[(size_t)warp * 32 + lane] = am + sbm[lane];
    float v = __expf(av + sbv[lane]);
    outv[(size_t)warp * 32 + lane] = fminf(fmaxf(v, 1e-8f), 100.0f);
}

// ---------------- host launch ----------------
extern "C" void kernel_launch(void* const* d_in, const int* in_sizes, int n_in,
                              void* d_out, int out_size) {
    const float* x = (const float*)d_in[0];
    const int* ei = (const int*)d_in[1];          // int64 in JAX source, int32 on device
    const float* W1 = (const float*)d_in[2];
    const float* as1 = (const float*)d_in[3];
    const float* ad1 = (const float*)d_in[4];
    const float* b1 = (const float*)d_in[5];
    const float* W2 = (const float*)d_in[6];
    const float* as2 = (const float*)d_in[7];
    const float* ad2 = (const float*)d_in[8];
    const float* b2 = (const float*)d_in[9];
    const float* W3 = (const float*)d_in[10];
    const float* as3 = (const float*)d_in[11];
    const float* ad3 = (const float*)d_in[12];
    const float* b3 = (const float*)d_in[13];
    const float* Wm = (const float*)d_in[14];
    const float* bm = (const float*)d_in[15];
    const float* Wv = (const float*)d_in[16];
    const float* bv = (const float*)d_in[17];

    float* out = (float*)d_out;
    float* zmean = out;
    float* zvar = out + (size_t)NN * 32;
    float* z = out + (size_t)2 * NN * 32;

    // ---- CSR build (reused by all 3 layers) ----
    deg_init<<<(NN + 255) / 256, 256>>>();
    deg_hist<<<(EE + 255) / 256, 256>>>(ei);
    scan_kernel<<<1, 1024>>>();
    scatter_kernel<<<(EE + NN + 255) / 256, 256>>>(ei);

    int agg_blocks = (NN + 7) / 8;  // one warp per node, 8 warps/block

    // ---- layer 1: 128 -> 4x64 ----
    sgemm<<<dim3(4, (NN + 63) / 64), 256>>>(x, 0, W1, NN, 128, 256);
    compute_alpha<4, 64><<<agg_blocks, 256>>>(as1, ad1);
    gat_aggregate<4, 64, true><<<agg_blocks, 256>>>(b1, nullptr, 1);

    // ---- layer 2: 64 -> 4x64 ----
    sgemm<<<dim3(4, (NN + 63) / 64), 256>>>(nullptr, 1, W2, NN, 64, 256);
    compute_alpha<4, 64><<<agg_blocks, 256>>>(as2, ad2);
    gat_aggregate<4, 64, true><<<agg_blocks, 256>>>(b2, nullptr, 2);

    // ---- layer 3: 64 -> 1x32 ----
    sgemm<<<dim3(1, (NN + 63) / 64), 256>>>(nullptr, 2, W3, NN, 64, 32);
    compute_alpha<1, 32><<<agg_blocks, 256>>>(as3, ad3);
    gat_aggregate<1, 32, false><<<agg_blocks, 256>>>(b3, z, 0);

    // ---- epilogue ----
    epilogue<<<agg_blocks, 256>>>(z, Wm, bm, Wv, bv, zmean, zvar);
}

// round 8
// speedup vs baseline: 1.2189x; 1.2189x over previous
#include <cuda_runtime.h>
#include <cuda_bf16.h>

#define NN 20000
#define EE 320000
#define IN_C 128
#define HID 64
#define OUT_C 32
#define NEG_SLOPE 0.2f

// ---------------- scratch (device globals; no allocation) ----------------
__device__ __align__(16) float g_h[NN * 256];   // GEMM output (max H*C = 256)
__device__ __align__(16) float g_f1[NN * 64];   // layer-1 node features
__device__ __align__(16) float g_f2[NN * 64];   // layer-2 node features
__device__ __align__(16) float g_as[NN * 4];    // alpha_src per node (max 4 heads)
__device__ __align__(16) float g_ad[NN * 4];    // alpha_dst per node
__device__ int   g_deg[NN];
__device__ int   g_rowptr[NN + 1];
__device__ int   g_cursor[NN];
__device__ int   g_col[EE + NN];                // CSR: src per incoming edge (incl. self loops)

// buffer selector: 0 = external pointer, 1 = g_f1, 2 = g_f2
__device__ __forceinline__ float* sel_buf(int sel, float* ext) {
    if (sel == 1) return g_f1;
    if (sel == 2) return g_f2;
    return ext;
}
__device__ __forceinline__ const float* sel_cbuf(int sel, const float* ext) {
    if (sel == 1) return g_f1;
    if (sel == 2) return g_f2;
    return ext;
}

// ---------------- CSR build ----------------
__global__ void deg_init() {
    int i = blockIdx.x * blockDim.x + threadIdx.x;
    if (i < NN) g_deg[i] = 1;  // self loop
}

__global__ void deg_hist(const int* __restrict__ ei) {
    int e = blockIdx.x * blockDim.x + threadIdx.x;
    if (e < EE) {
        int d = ei[EE + e];
        atomicAdd(&g_deg[d], 1);
    }
}

__global__ void scan_kernel() {
    __shared__ int warpsum[32];
    __shared__ int carry_s;
    int tid = threadIdx.x, lane = tid & 31, wid = tid >> 5;
    if (tid == 0) { carry_s = 0; g_rowptr[0] = 0; }
    __syncthreads();
    for (int base = 0; base < NN; base += 1024) {
        int i = base + tid;
        int v = (i < NN) ? g_deg[i] : 0;
        int x = v;
#pragma unroll
        for (int off = 1; off < 32; off <<= 1) {
            int t = __shfl_up_sync(0xffffffffu, x, off);
            if (lane >= off) x += t;
        }
        if (lane == 31) warpsum[wid] = x;
        __syncthreads();
        if (wid == 0) {
            int w = warpsum[lane];
#pragma unroll
            for (int off = 1; off < 32; off <<= 1) {
                int t = __shfl_up_sync(0xffffffffu, w, off);
                if (lane >= off) w += t;
            }
            warpsum[lane] = w;
        }
        __syncthreads();
        int prefix = (wid > 0 ? warpsum[wid - 1] : 0) + carry_s;
        int incl = prefix + x;
        if (i < NN) { g_rowptr[i + 1] = incl; g_cursor[i] = incl - v; }
        __syncthreads();
        if (tid == 0) carry_s += warpsum[31];
        __syncthreads();
    }
}

__global__ void scatter_kernel(const int* __restrict__ ei) {
    int id = blockIdx.x * blockDim.x + threadIdx.x;
    if (id >= EE + NN) return;
    int s, d;
    if (id < EE) { s = ei[id]; d = ei[EE + id]; }
    else { s = d = id - EE; }
    int pos = atomicAdd(&g_cursor[d], 1);
    g_col[pos] = s;
}

// ---------------- tf32 tensor-core GEMM: g_h[Nr,M] = A[Nr,K] @ B[K,M] ----------------
__device__ __forceinline__ unsigned f2tf32(float x) {
    unsigned r;
    asm("cvt.rna.tf32.f32 %0, %1;" : "=r"(r) : "f"(x));
    return r;
}

__device__ __forceinline__ void mma_tf32(float& c0, float& c1, float& c2, float& c3,
                                         unsigned a0, unsigned a1, unsigned a2, unsigned a3,
                                         unsigned b0, unsigned b1) {
    asm volatile(
        "mma.sync.aligned.m16n8k8.row.col.f32.tf32.tf32.f32 "
        "{%0,%1,%2,%3},{%4,%5,%6,%7},{%8,%9},{%0,%1,%2,%3};"
        : "+f"(c0), "+f"(c1), "+f"(c2), "+f"(c3)
        : "r"(a0), "r"(a1), "r"(a2), "r"(a3), "r"(b0), "r"(b1));
}

// Block tile 128(M) x 64(N) x 32(K); 256 threads = 8 warps in 4(M) x 2(N) grid,
// each warp computes 32x32 as 2x4 m16n8k8 fragments.
// As stride 36 -> fragment LDS bank = (4g+t) conflict-free.
// Bs stride 72 -> fragment LDS bank = (8t+g) conflict-free.
__global__ void mm_tf32(const float* __restrict__ Aext, int Asel,
                        const float* __restrict__ B, int Nr, int K, int M) {
    const float* A = sel_cbuf(Asel, Aext);
    float* C = g_h;
    __shared__ unsigned As[128 * 36];
    __shared__ unsigned Bs[32 * 72];
    int tid = threadIdx.x;
    int lane = tid & 31;
    int w = tid >> 5;
    int wm = w & 3;        // 0..3 -> M offset wm*32
    int wn = w >> 2;       // 0..1 -> N offset wn*32
    int g = lane >> 2;     // groupID 0..7
    int t = lane & 3;      // threadID_in_group 0..3
    int row0 = blockIdx.y * 128;
    int col0 = blockIdx.x * 64;

    float acc[2][4][4];
#pragma unroll
    for (int mi = 0; mi < 2; mi++)
#pragma unroll
        for (int ni = 0; ni < 4; ni++)
#pragma unroll
            for (int q = 0; q < 4; q++) acc[mi][ni][q] = 0.f;

    for (int kt = 0; kt < K; kt += 32) {
        // stage A: 128x32 floats, tf32-rounded
#pragma unroll
        for (int i = 0; i < 4; i++) {
            int lin = tid + i * 256;        // 0..1023
            int r = lin >> 3;               // 0..127
            int c4 = (lin & 7) * 4;         // 0..28
            float4 v = make_float4(0.f, 0.f, 0.f, 0.f);
            if (row0 + r < Nr)
                v = *(const float4*)(A + (size_t)(row0 + r) * K + kt + c4);
            uint4 u = make_uint4(f2tf32(v.x), f2tf32(v.y), f2tf32(v.z), f2tf32(v.w));
            *(uint4*)&As[r * 36 + c4] = u;
        }
        // stage B: 32x64 floats, tf32-rounded (zero-pad cols >= M)
#pragma unroll
        for (int i = 0; i < 2; i++) {
            int lin = tid + i * 256;        // 0..511
            int kk = lin >> 4;              // 0..31
            int c4 = (lin & 15) * 4;        // 0..60
            float4 v = make_float4(0.f, 0.f, 0.f, 0.f);
            if (col0 + c4 + 4 <= M) {
                v = *(const float4*)(B + (size_t)(kt + kk) * M + col0 + c4);
            } else if (col0 + c4 < M) {
                const float* br = B + (size_t)(kt + kk) * M;
                v.x = br[col0 + c4];
                if (col0 + c4 + 1 < M) v.y = br[col0 + c4 + 1];
                if (col0 + c4 + 2 < M) v.z = br[col0 + c4 + 2];
            }
            uint4 u = make_uint4(f2tf32(v.x), f2tf32(v.y), f2tf32(v.z), f2tf32(v.w));
            *(uint4*)&Bs[kk * 72 + c4] = u;
        }
        __syncthreads();

#pragma unroll
        for (int kk = 0; kk < 32; kk += 8) {
            unsigned a[2][4], b[4][2];
#pragma unroll
            for (int mi = 0; mi < 2; mi++) {
                int rowA = wm * 32 + mi * 16 + g;
                a[mi][0] = As[rowA * 36 + kk + t];
                a[mi][1] = As[(rowA + 8) * 36 + kk + t];
                a[mi][2] = As[rowA * 36 + kk + t + 4];
                a[mi][3] = As[(rowA + 8) * 36 + kk + t + 4];
            }
#pragma unroll
            for (int ni = 0; ni < 4; ni++) {
                int colB = wn * 32 + ni * 8 + g;
                b[ni][0] = Bs[(kk + t) * 72 + colB];
                b[ni][1] = Bs[(kk + t + 4) * 72 + colB];
            }
#pragma unroll
            for (int mi = 0; mi < 2; mi++)
#pragma unroll
                for (int ni = 0; ni < 4; ni++)
                    mma_tf32(acc[mi][ni][0], acc[mi][ni][1], acc[mi][ni][2], acc[mi][ni][3],
                             a[mi][0], a[mi][1], a[mi][2], a[mi][3], b[ni][0], b[ni][1]);
        }
        __syncthreads();
    }

    // store C
#pragma unroll
    for (int mi = 0; mi < 2; mi++) {
#pragma unroll
        for (int ni = 0; ni < 4; ni++) {
            int r = row0 + wm * 32 + mi * 16 + g;
            int c = col0 + wn * 32 + ni * 8 + 2 * t;
            if (r < Nr && c < M) {
                C[(size_t)r * M + c] = acc[mi][ni][0];
                if (c + 1 < M) C[(size_t)r * M + c + 1] = acc[mi][ni][1];
            }
            if (r + 8 < Nr && c < M) {
                C[(size_t)(r + 8) * M + c] = acc[mi][ni][2];
                if (c + 1 < M) C[(size_t)(r + 8) * M + c + 1] = acc[mi][ni][3];
            }
        }
    }
}

// ---------------- alpha = einsum('nhc,hc->nh'), h = g_h ----------------
template <int H, int C>
__global__ void compute_alpha(const float* __restrict__ a_s, const float* __restrict__ a_d) {
    constexpr int HC = H * C;
    constexpr int SLOTS = HC / 32;
    int warp = (blockIdx.x * blockDim.x + threadIdx.x) >> 5;
    int lane = threadIdx.x & 31;
    if (warp >= NN) return;
    float ps[H], pd[H];
#pragma unroll
    for (int hh = 0; hh < H; hh++) { ps[hh] = 0.f; pd[hh] = 0.f; }
    const float* hr = g_h + (size_t)warp * HC;
#pragma unroll
    for (int k = 0; k < SLOTS; k++) {
        int flat = lane + 32 * k;
        float v = hr[flat];
        ps[(32 * k) / C] = fmaf(v, a_s[flat], ps[(32 * k) / C]);
        pd[(32 * k) / C] = fmaf(v, a_d[flat], pd[(32 * k) / C]);
    }
#pragma unroll
    for (int hh = 0; hh < H; hh++) {
#pragma unroll
        for (int off = 16; off > 0; off >>= 1) {
            ps[hh] += __shfl_xor_sync(0xffffffffu, ps[hh], off);
            pd[hh] += __shfl_xor_sync(0xffffffffu, pd[hh], off);
        }
    }
    if (lane == 0) {
#pragma unroll
        for (int hh = 0; hh < H; hh++) {
            g_as[warp * H + hh] = ps[hh];
            g_ad[warp * H + hh] = pd[hh];
        }
    }
}

// ---------------- GAT softmax-aggregate, one warp per dst node ----------------
__device__ __forceinline__ float leaky(float x) { return x > 0.f ? x : NEG_SLOPE * x; }

template <int H, int C, bool RELU>
__global__ void gat_aggregate(const float* __restrict__ bias, float* __restrict__ out_ext,
                              int out_sel) {
    constexpr int HC = H * C;
    constexpr int SLOTS = HC / 32;
    constexpr int CG = C / 32;
    const float* h = g_h;
    float* out = sel_buf(out_sel, out_ext);
    int warp = (blockIdx.x * blockDim.x + threadIdx.x) >> 5;
    int lane = threadIdx.x & 31;
    if (warp >= NN) return;
    int n = warp;
    int beg = g_rowptr[n], end = g_rowptr[n + 1];

    float ad[H];
    if (H == 4) {
        float4 a = ((const float4*)g_ad)[n];
        ad[0] = a.x;
        if (H > 1) { ad[1] = a.y; ad[2] = a.z; ad[3] = a.w; }
    } else {
        ad[0] = g_ad[n * H];
    }

    // pass 1: per-head max of edge logits
    float m[H];
#pragma unroll
    for (int hh = 0; hh < H; hh++) m[hh] = -1e30f;
    for (int j = beg + lane; j < end; j += 32) {
        int s = g_col[j];
        if (H == 4) {
            float4 a = ((const float4*)g_as)[s];
            float as4[4] = {a.x, a.y, a.z, a.w};
#pragma unroll
            for (int hh = 0; hh < 4; hh++)
                m[hh] = fmaxf(m[hh], leaky(as4[hh] + ad[hh]));
        } else {
            m[0] = fmaxf(m[0], leaky(g_as[s * H] + ad[0]));
        }
    }
#pragma unroll
    for (int hh = 0; hh < H; hh++)
#pragma unroll
        for (int off = 16; off > 0; off >>= 1)
            m[hh] = fmaxf(m[hh], __shfl_xor_sync(0xffffffffu, m[hh], off));

    // pass 2: exp-sum + message accumulation
    float acc[SLOTS];
#pragma unroll
    for (int k = 0; k < SLOTS; k++) acc[k] = 0.f;
    float ssum[H];
#pragma unroll
    for (int hh = 0; hh < H; hh++) ssum[hh] = 0.f;

    for (int base = beg; base < end; base += 32) {
        int cnt = min(32, end - base);
        int sj = 0;
        float p[H];
#pragma unroll
        for (int hh = 0; hh < H; hh++) p[hh] = 0.f;
        if (lane < cnt) {
            sj = g_col[base + lane];
            if (H == 4) {
                float4 a = ((const float4*)g_as)[sj];
                float as4[4] = {a.x, a.y, a.z, a.w};
#pragma unroll
                for (int hh = 0; hh < 4; hh++) {
                    p[hh] = __expf(leaky(as4[hh] + ad[hh]) - m[hh]);
                    ssum[hh] += p[hh];
                }
            } else {
                p[0] = __expf(leaky(g_as[sj * H] + ad[0]) - m[0]);
                ssum[0] += p[0];
            }
        }
        for (int t = 0; t < cnt; ++t) {
            int src = __shfl_sync(0xffffffffu, sj, t);
            float pb[H];
#pragma unroll
            for (int hh = 0; hh < H; hh++)
                pb[hh] = __shfl_sync(0xffffffffu, p[hh], t);
            const float* hrow = h + (size_t)src * HC;
#pragma unroll
            for (int k = 0; k < SLOTS; k++)
                acc[k] = fmaf(pb[(32 * k) / C], hrow[lane + 32 * k], acc[k]);
        }
    }
#pragma unroll
    for (int hh = 0; hh < H; hh++)
#pragma unroll
        for (int off = 16; off > 0; off >>= 1)
            ssum[hh] += __shfl_xor_sync(0xffffffffu, ssum[hh], off);

    float inv[H];
#pragma unroll
    for (int hh = 0; hh < H; hh++) inv[hh] = 1.f / (ssum[hh] + 1e-16f);

#pragma unroll
    for (int g = 0; g < CG; g++) {
        int c = lane + 32 * g;
        float v = 0.f;
#pragma unroll
        for (int hh = 0; hh < H; hh++) v += acc[g + CG * hh] * inv[hh];
        v = v * (1.0f / H) + bias[c];
        if (RELU) v = fmaxf(v, 0.f);
        out[(size_t)n * C + c] = v;
    }
}

// ---------------- epilogue: z_mean, z_var ----------------
__global__ void epilogue(const float* __restrict__ z, const float* __restrict__ Wm,
                         const float* __restrict__ bm, const float* __restrict__ Wv,
                         const float* __restrict__ bv, float* __restrict__ outm,
                         float* __restrict__ outv) {
    __shared__ float sWm[1024], sWv[1024], sbm[32], sbv[32];
    int tid = threadIdx.x;
    for (int i = tid; i < 1024; i += blockDim.x) { sWm[i] = Wm[i]; sWv[i] = Wv[i]; }
    if (tid < 32) { sbm[tid] = bm[tid]; sbv[tid] = bv[tid]; }
    __syncthreads();
    int warp = (blockIdx.x * blockDim.x + tid) >> 5;
    int lane = tid & 31;
    if (warp >= NN) return;
    float zc = z[(size_t)warp * 32 + lane];
    float am = 0.f, av = 0.f;
#pragma unroll
    for (int k = 0; k < 32; k++) {
        float zk = __shfl_sync(0xffffffffu, zc, k);
        am = fmaf(zk, sWm[k * 32 + lane], am);
        av = fmaf(zk, sWv[k * 32 + lane], av);
    }
    outm[(size_t)warp * 32 + lane] = am + sbm[lane];
    float v = __expf(av + sbv[lane]);
    outv[(size_t)warp * 32 + lane] = fminf(fmaxf(v, 1e-8f), 100.0f);
}

// ---------------- host launch ----------------
extern "C" void kernel_launch(void* const* d_in, const int* in_sizes, int n_in,
                              void* d_out, int out_size) {
    const float* x = (const float*)d_in[0];
    const int* ei = (const int*)d_in[1];          // int64 in JAX source, int32 on device
    const float* W1 = (const float*)d_in[2];
    const float* as1 = (const float*)d_in[3];
    const float* ad1 = (const float*)d_in[4];
    const float* b1 = (const float*)d_in[5];
    const float* W2 = (const float*)d_in[6];
    const float* as2 = (const float*)d_in[7];
    const float* ad2 = (const float*)d_in[8];
    const float* b2 = (const float*)d_in[9];
    const float* W3 = (const float*)d_in[10];
    const float* as3 = (const float*)d_in[11];
    const float* ad3 = (const float*)d_in[12];
    const float* b3 = (const float*)d_in[13];
    const float* Wm = (const float*)d_in[14];
    const float* bm = (const float*)d_in[15];
    const float* Wv = (const float*)d_in[16];
    const float* bv = (const float*)d_in[17];

    float* out = (float*)d_out;
    float* zmean = out;
    float* zvar = out + (size_t)NN * 32;
    float* z = out + (size_t)2 * NN * 32;

    // ---- CSR build (reused by all 3 layers) ----
    deg_init<<<(NN + 255) / 256, 256>>>();
    deg_hist<<<(EE + 255) / 256, 256>>>(ei);
    scan_kernel<<<1, 1024>>>();
    scatter_kernel<<<(EE + NN + 255) / 256, 256>>>(ei);

    int agg_blocks = (NN + 7) / 8;  // one warp per node, 8 warps/block
    int gemm_rows = (NN + 127) / 128;

    // ---- layer 1: 128 -> 4x64 ----
    mm_tf32<<<dim3(4, gemm_rows), 256>>>(x, 0, W1, NN, 128, 256);
    compute_alpha<4, 64><<<agg_blocks, 256>>>(as1, ad1);
    gat_aggregate<4, 64, true><<<agg_blocks, 256>>>(b1, nullptr, 1);

    // ---- layer 2: 64 -> 4x64 ----
    mm_tf32<<<dim3(4, gemm_rows), 256>>>(nullptr, 1, W2, NN, 64, 256);
    compute_alpha<4, 64><<<agg_blocks, 256>>>(as2, ad2);
    gat_aggregate<4, 64, true><<<agg_blocks, 256>>>(b2, nullptr, 2);

    // ---- layer 3: 64 -> 1x32 ----
    mm_tf32<<<dim3(1, gemm_rows), 256>>>(nullptr, 2, W3, NN, 64, 32);
    compute_alpha<1, 32><<<agg_blocks, 256>>>(as3, ad3);
    gat_aggregate<1, 32, false><<<agg_blocks, 256>>>(b3, z, 0);

    // ---- epilogue ----
    epilogue<<<agg_blocks, 256>>>(z, Wm, bm, Wv, bv, zmean, zvar);
}

// round 10
// speedup vs baseline: 1.3159x; 1.0796x over previous
#include <cuda_runtime.h>
#include <cuda_fp16.h>
#include <cuda_bf16.h>

#define NN 20000
#define EE 320000
#define IN_C 128
#define HID 64
#define OUT_C 32
#define NEG_SLOPE 0.2f

// ---------------- scratch (device globals; no allocation) ----------------
__device__ __align__(16) __half g_hh[NN * 256]; // GEMM output h in fp16 (max H*C = 256)
__device__ __align__(16) float g_f1[NN * 64];   // layer-1 node features (fp32)
__device__ __align__(16) float g_f2[NN * 64];   // layer-2 node features (fp32)
__device__ __align__(16) float g_as[NN * 4];    // alpha_src per node (max 4 heads)
__device__ __align__(16) float g_ad[NN * 4];    // alpha_dst per node
__device__ int   g_deg[NN];
__device__ int   g_rowptr[NN + 1];
__device__ int   g_cursor[NN];
__device__ int   g_col[EE + NN];                // CSR: src per incoming edge (incl. self loops)

// buffer selector: 0 = external pointer, 1 = g_f1, 2 = g_f2
__device__ __forceinline__ float* sel_buf(int sel, float* ext) {
    if (sel == 1) return g_f1;
    if (sel == 2) return g_f2;
    return ext;
}
__device__ __forceinline__ const float* sel_cbuf(int sel, const float* ext) {
    if (sel == 1) return g_f1;
    if (sel == 2) return g_f2;
    return ext;
}

// ---------------- CSR build ----------------
__global__ void deg_init() {
    int i = blockIdx.x * blockDim.x + threadIdx.x;
    if (i < NN) g_deg[i] = 1;  // self loop
}

__global__ void deg_hist(const int* __restrict__ ei) {
    int e = blockIdx.x * blockDim.x + threadIdx.x;
    if (e < EE) {
        int d = ei[EE + e];
        atomicAdd(&g_deg[d], 1);
    }
}

__global__ void scan_kernel() {
    __shared__ int warpsum[32];
    __shared__ int carry_s;
    int tid = threadIdx.x, lane = tid & 31, wid = tid >> 5;
    if (tid == 0) { carry_s = 0; g_rowptr[0] = 0; }
    __syncthreads();
    for (int base = 0; base < NN; base += 1024) {
        int i = base + tid;
        int v = (i < NN) ? g_deg[i] : 0;
        int x = v;
#pragma unroll
        for (int off = 1; off < 32; off <<= 1) {
            int t = __shfl_up_sync(0xffffffffu, x, off);
            if (lane >= off) x += t;
        }
        if (lane == 31) warpsum[wid] = x;
        __syncthreads();
        if (wid == 0) {
            int w = warpsum[lane];
#pragma unroll
            for (int off = 1; off < 32; off <<= 1) {
                int t = __shfl_up_sync(0xffffffffu, w, off);
                if (lane >= off) w += t;
            }
            warpsum[lane] = w;
        }
        __syncthreads();
        int prefix = (wid > 0 ? warpsum[wid - 1] : 0) + carry_s;
        int incl = prefix + x;
        if (i < NN) { g_rowptr[i + 1] = incl; g_cursor[i] = incl - v; }
        __syncthreads();
        if (tid == 0) carry_s += warpsum[31];
        __syncthreads();
    }
}

__global__ void scatter_kernel(const int* __restrict__ ei) {
    int id = blockIdx.x * blockDim.x + threadIdx.x;
    if (id >= EE + NN) return;
    int s, d;
    if (id < EE) { s = ei[id]; d = ei[EE + id]; }
    else { s = d = id - EE; }
    int pos = atomicAdd(&g_cursor[d], 1);
    g_col[pos] = s;
}

// ---------------- tf32 tensor-core GEMM + fused alpha ----------------
// h[Nr,M] = A[Nr,K] @ B[K,M], stored fp16 to g_hh.
// Each block-column tile (64 cols) covers exactly one head (Cc cols, Cc<=64);
// alpha_s/alpha_d for (row, head) computed from fp32 accumulators in-register.
__device__ __forceinline__ unsigned f2tf32(float x) {
    unsigned r;
    asm("cvt.rna.tf32.f32 %0, %1;" : "=r"(r) : "f"(x));
    return r;
}

__device__ __forceinline__ void mma_tf32(float& c0, float& c1, float& c2, float& c3,
                                         unsigned a0, unsigned a1, unsigned a2, unsigned a3,
                                         unsigned b0, unsigned b1) {
    asm volatile(
        "mma.sync.aligned.m16n8k8.row.col.f32.tf32.tf32.f32 "
        "{%0,%1,%2,%3},{%4,%5,%6,%7},{%8,%9},{%0,%1,%2,%3};"
        : "+f"(c0), "+f"(c1), "+f"(c2), "+f"(c3)
        : "r"(a0), "r"(a1), "r"(a2), "r"(a3), "r"(b0), "r"(b1));
}

// Block tile 128(M) x 64(N) x 32(K); 256 threads = 8 warps in 4(M) x 2(N) grid,
// each warp computes 32x32 as 2x4 m16n8k8 fragments.
__global__ void mm_tf32(const float* __restrict__ Aext, int Asel,
                        const float* __restrict__ B,
                        const float* __restrict__ avs, const float* __restrict__ avd,
                        int Nr, int K, int M, int Cc, int H) {
    const float* A = sel_cbuf(Asel, Aext);
    __shared__ unsigned As[128 * 36];
    __shared__ unsigned Bs[32 * 72];
    __shared__ float sAv[64], sDv[64];
    int tid = threadIdx.x;
    int lane = tid & 31;
    int w = tid >> 5;
    int wm = w & 3;        // 0..3 -> M offset wm*32
    int wn = w >> 2;       // 0..1 -> N offset wn*32
    int g = lane >> 2;     // groupID 0..7
    int t = lane & 3;      // threadID_in_group 0..3
    int row0 = blockIdx.y * 128;
    int col0 = blockIdx.x * 64;
    int head = blockIdx.x;  // valid: Cc==64 tiles align with heads; layer3 Cc=32 single tile head 0

    // stage attention vectors for this head
    if (tid < 64) sAv[tid] = (tid < Cc) ? avs[head * Cc + tid] : 0.f;
    else if (tid < 128) sDv[tid - 64] = (tid - 64 < Cc) ? avd[head * Cc + (tid - 64)] : 0.f;

    float acc[2][4][4];
#pragma unroll
    for (int mi = 0; mi < 2; mi++)
#pragma unroll
        for (int ni = 0; ni < 4; ni++)
#pragma unroll
            for (int q = 0; q < 4; q++) acc[mi][ni][q] = 0.f;

    for (int kt = 0; kt < K; kt += 32) {
        // stage A: 128x32 floats, tf32-rounded
#pragma unroll
        for (int i = 0; i < 4; i++) {
            int lin = tid + i * 256;        // 0..1023
            int r = lin >> 3;               // 0..127
            int c4 = (lin & 7) * 4;         // 0..28
            float4 v = make_float4(0.f, 0.f, 0.f, 0.f);
            if (row0 + r < Nr)
                v = *(const float4*)(A + (size_t)(row0 + r) * K + kt + c4);
            uint4 u = make_uint4(f2tf32(v.x), f2tf32(v.y), f2tf32(v.z), f2tf32(v.w));
            *(uint4*)&As[r * 36 + c4] = u;
        }
        // stage B: 32x64 floats, tf32-rounded (zero-pad cols >= M)
#pragma unroll
        for (int i = 0; i < 2; i++) {
            int lin = tid + i * 256;        // 0..511
            int kk = lin >> 4;              // 0..31
            int c4 = (lin & 15) * 4;        // 0..60
            float4 v = make_float4(0.f, 0.f, 0.f, 0.f);
            if (col0 + c4 + 4 <= M) {
                v = *(const float4*)(B + (size_t)(kt + kk) * M + col0 + c4);
            } else if (col0 + c4 < M) {
                const float* br = B + (size_t)(kt + kk) * M;
                v.x = br[col0 + c4];
                if (col0 + c4 + 1 < M) v.y = br[col0 + c4 + 1];
                if (col0 + c4 + 2 < M) v.z = br[col0 + c4 + 2];
            }
            uint4 u = make_uint4(f2tf32(v.x), f2tf32(v.y), f2tf32(v.z), f2tf32(v.w));
            *(uint4*)&Bs[kk * 72 + c4] = u;
        }
        __syncthreads();

#pragma unroll
        for (int kk = 0; kk < 32; kk += 8) {
            unsigned a[2][4], b[4][2];
#pragma unroll
            for (int mi = 0; mi < 2; mi++) {
                int rowA = wm * 32 + mi * 16 + g;
                a[mi][0] = As[rowA * 36 + kk + t];
                a[mi][1] = As[(rowA + 8) * 36 + kk + t];
                a[mi][2] = As[rowA * 36 + kk + t + 4];
                a[mi][3] = As[(rowA + 8) * 36 + kk + t + 4];
            }
#pragma unroll
            for (int ni = 0; ni < 4; ni++) {
                int colB = wn * 32 + ni * 8 + g;
                b[ni][0] = Bs[(kk + t) * 72 + colB];
                b[ni][1] = Bs[(kk + t + 4) * 72 + colB];
            }
#pragma unroll
            for (int mi = 0; mi < 2; mi++)
#pragma unroll
                for (int ni = 0; ni < 4; ni++)
                    mma_tf32(acc[mi][ni][0], acc[mi][ni][1], acc[mi][ni][2], acc[mi][ni][3],
                             a[mi][0], a[mi][1], a[mi][2], a[mi][3], b[ni][0], b[ni][1]);
        }
        __syncthreads();
    }

    // store h as fp16 (half2 per fragment pair)
#pragma unroll
    for (int mi = 0; mi < 2; mi++) {
#pragma unroll
        for (int ni = 0; ni < 4; ni++) {
            int r = row0 + wm * 32 + mi * 16 + g;
            int c = col0 + wn * 32 + ni * 8 + 2 * t;
            if (r < Nr && c < M)
                *(half2*)&g_hh[(size_t)r * M + c] = __floats2half2_rn(acc[mi][ni][0], acc[mi][ni][1]);
            if (r + 8 < Nr && c < M)
                *(half2*)&g_hh[(size_t)(r + 8) * M + c] = __floats2half2_rn(acc[mi][ni][2], acc[mi][ni][3]);
        }
    }

    // ---- fused alpha: per-row dot with a_src / a_dst over this head's cols ----
    float rp_s[4] = {0.f, 0.f, 0.f, 0.f};
    float rp_d[4] = {0.f, 0.f, 0.f, 0.f};
#pragma unroll
    for (int mi = 0; mi < 2; mi++)
#pragma unroll
        for (int ni = 0; ni < 4; ni++) {
            int cl = wn * 32 + ni * 8 + 2 * t;  // col within tile == col within head
            float a0 = sAv[cl], a1 = sAv[cl + 1];
            float d0 = sDv[cl], d1 = sDv[cl + 1];
#pragma unroll
            for (int half = 0; half < 2; half++) {
                float x0 = acc[mi][ni][2 * half];
                float x1 = acc[mi][ni][2 * half + 1];
                rp_s[mi * 2 + half] += x0 * a0 + x1 * a1;
                rp_d[mi * 2 + half] += x0 * d0 + x1 * d1;
            }
        }
    // reduce over t (lane bits 0,1)
#pragma unroll
    for (int i = 0; i < 4; i++) {
#pragma unroll
        for (int off = 1; off <= 2; off <<= 1) {
            rp_s[i] += __shfl_xor_sync(0xffffffffu, rp_s[i], off);
            rp_d[i] += __shfl_xor_sync(0xffffffffu, rp_d[i], off);
        }
    }
    float* red = (float*)As;  // reuse smem: [0..127]=s, [128..255]=d
    if (tid < 256) red[tid] = 0.f;
    __syncthreads();
    if (t == 0) {
#pragma unroll
        for (int mi = 0; mi < 2; mi++)
#pragma unroll
            for (int half = 0; half < 2; half++) {
                int rowl = wm * 32 + mi * 16 + half * 8 + g;
                atomicAdd(&red[rowl], rp_s[mi * 2 + half]);
                atomicAdd(&red[128 + rowl], rp_d[mi * 2 + half]);
            }
    }
    __syncthreads();
    if (tid < 128) {
        int r = row0 + tid;
        if (r < Nr) {
            g_as[(size_t)r * H + head] = red[tid];
            g_ad[(size_t)r * H + head] = red[128 + tid];
        }
    }
}

// ---------------- GAT softmax-aggregate, one warp per dst node, fp16 gather ----------------
__device__ __forceinline__ float leaky(float x) { return x > 0.f ? x : NEG_SLOPE * x; }

template <int H, int C, bool RELU>
__global__ void gat_aggregate(const float* __restrict__ bias, float* __restrict__ out_ext,
                              int out_sel) {
    constexpr int HC = H * C;
    constexpr int PAIRS = HC / 2;                      // half2 per row
    constexpr int K2 = (PAIRS + 31) / 32;              // half2 per lane (4 for H4C64, 1 for H1C32)
    constexpr bool FULL = (PAIRS >= 32);
    float* out = sel_buf(out_sel, out_ext);
    int warp = (blockIdx.x * blockDim.x + threadIdx.x) >> 5;
    int lane = threadIdx.x & 31;
    if (warp >= NN) return;
    int n = warp;
    int beg = g_rowptr[n], end = g_rowptr[n + 1];

    float ad[H];
    if (H == 4) {
        float4 a = ((const float4*)g_ad)[n];
        ad[0] = a.x; ad[1] = a.y; ad[2] = a.z; ad[3] = a.w;
    } else {
        ad[0] = g_ad[n];
    }

    // pass 1: per-head max of edge logits
    float m[H];
#pragma unroll
    for (int hh = 0; hh < H; hh++) m[hh] = -1e30f;
    for (int j = beg + lane; j < end; j += 32) {
        int s = g_col[j];
        if (H == 4) {
            float4 a = ((const float4*)g_as)[s];
            float as4[4] = {a.x, a.y, a.z, a.w};
#pragma unroll
            for (int hh = 0; hh < 4; hh++)
                m[hh] = fmaxf(m[hh], leaky(as4[hh] + ad[hh]));
        } else {
            m[0] = fmaxf(m[0], leaky(g_as[s] + ad[0]));
        }
    }
#pragma unroll
    for (int hh = 0; hh < H; hh++)
#pragma unroll
        for (int off = 16; off > 0; off >>= 1)
            m[hh] = fmaxf(m[hh], __shfl_xor_sync(0xffffffffu, m[hh], off));

    // pass 2: exp-sum + fp16 message accumulation
    float2 acc[K2];
#pragma unroll
    for (int k = 0; k < K2; k++) acc[k] = make_float2(0.f, 0.f);
    float ssum[H];
#pragma unroll
    for (int hh = 0; hh < H; hh++) ssum[hh] = 0.f;

    const __half2* hbase = (const __half2*)g_hh;

    for (int base = beg; base < end; base += 32) {
        int cnt = min(32, end - base);
        int sj = 0;
        float p[H];
#pragma unroll
        for (int hh = 0; hh < H; hh++) p[hh] = 0.f;
        if (lane < cnt) {
            sj = g_col[base + lane];
            if (H == 4) {
                float4 a = ((const float4*)g_as)[sj];
                float as4[4] = {a.x, a.y, a.z, a.w};
#pragma unroll
                for (int hh = 0; hh < 4; hh++) {
                    p[hh] = __expf(leaky(as4[hh] + ad[hh]) - m[hh]);
                    ssum[hh] += p[hh];
                }
            } else {
                p[0] = __expf(leaky(g_as[sj] + ad[0]) - m[0]);
                ssum[0] += p[0];
            }
        }
        for (int t = 0; t < cnt; ++t) {
            int src = __shfl_sync(0xffffffffu, sj, t);
            float pb[H];
#pragma unroll
            for (int hh = 0; hh < H; hh++)
                pb[hh] = __shfl_sync(0xffffffffu, p[hh], t);
            const __half2* hrow = hbase + (size_t)src * PAIRS;
            if (FULL || lane < PAIRS) {
#pragma unroll
                for (int k = 0; k < K2; k++) {
                    float2 f = __half22float2(hrow[lane + 32 * k]);
                    // head of slot k: pairs 32k..32k+31 -> channels 64k.. => head = (2*32k)/C
                    constexpr int dummy = 0; (void)dummy;
                    int hh = (64 * k) / C;
                    acc[k].x = fmaf(pb[hh], f.x, acc[k].x);
                    acc[k].y = fmaf(pb[hh], f.y, acc[k].y);
                }
            }
        }
    }
#pragma unroll
    for (int hh = 0; hh < H; hh++)
#pragma unroll
        for (int off = 16; off > 0; off >>= 1)
            ssum[hh] += __shfl_xor_sync(0xffffffffu, ssum[hh], off);

    float inv[H];
#pragma unroll
    for (int hh = 0; hh < H; hh++) inv[hh] = 1.f / (ssum[hh] + 1e-16f);

    // output: each lane owns channel pair (2*lane, 2*lane+1) within each head's C;
    // mean over heads: acc[k] is head k's same channel-in-head pair (H4C64),
    // or the single head (H1C32, lanes < 16).
    if (FULL || lane < PAIRS) {
        float vx = 0.f, vy = 0.f;
#pragma unroll
        for (int k = 0; k < K2; k++) {
            int hh = (64 * k) / C;
            vx += acc[k].x * inv[hh];
            vy += acc[k].y * inv[hh];
        }
        int c = 2 * lane;  // channel within head
        vx = vx * (1.0f / H) + bias[c];
        vy = vy * (1.0f / H) + bias[c + 1];
        if (RELU) { vx = fmaxf(vx, 0.f); vy = fmaxf(vy, 0.f); }
        *(float2*)&out[(size_t)n * C + c] = make_float2(vx, vy);
    }
}

// ---------------- epilogue: z_mean, z_var ----------------
__global__ void epilogue(const float* __restrict__ z, const float* __restrict__ Wm,
                         const float* __restrict__ bm, const float* __restrict__ Wv,
                         const float* __restrict__ bv, float* __restrict__ outm,
                         float* __restrict__ outv) {
    __shared__ float sWm[1024], sWv[1024], sbm[32], sbv[32];
    int tid = threadIdx.x;
    for (int i = tid; i < 1024; i += blockDim.x) { sWm[i] = Wm[i]; sWv[i] = Wv[i]; }
    if (tid < 32) { sbm[tid] = bm[tid]; sbv[tid] = bv[tid]; }
    __syncthreads();
    int warp = (blockIdx.x * blockDim.x + tid) >> 5;
    int lane = tid & 31;
    if (warp >= NN) return;
    float zc = z[(size_t)warp * 32 + lane];
    float am = 0.f, av = 0.f;
#pragma unroll
    for (int k = 0; k < 32; k++) {
        float zk = __shfl_sync(0xffffffffu, zc, k);
        am = fmaf(zk, sWm[k * 32 + lane], am);
        av = fmaf(zk, sWv[k * 32 + lane], av);
    }
    outm[(size_t)warp * 32 + lane] = am + sbm[lane];
    float v = __expf(av + sbv[lane]);
    outv[(size_t)warp * 32 + lane] = fminf(fmaxf(v, 1e-8f), 100.0f);
}

// ---------------- host launch ----------------
extern "C" void kernel_launch(void* const* d_in, const int* in_sizes, int n_in,
                              void* d_out, int out_size) {
    const float* x = (const float*)d_in[0];
    const int* ei = (const int*)d_in[1];          // int64 in JAX source, int32 on device
    const float* W1 = (const float*)d_in[2];
    const float* as1 = (const float*)d_in[3];
    const float* ad1 = (const float*)d_in[4];
    const float* b1 = (const float*)d_in[5];
    const float* W2 = (const float*)d_in[6];
    const float* as2 = (const float*)d_in[7];
    const float* ad2 = (const float*)d_in[8];
    const float* b2 = (const float*)d_in[9];
    const float* W3 = (const float*)d_in[10];
    const float* as3 = (const float*)d_in[11];
    const float* ad3 = (const float*)d_in[12];
    const float* b3 = (const float*)d_in[13];
    const float* Wm = (const float*)d_in[14];
    const float* bm = (const float*)d_in[15];
    const float* Wv = (const float*)d_in[16];
    const float* bv = (const float*)d_in[17];

    float* out = (float*)d_out;
    float* zmean = out;
    float* zvar = out + (size_t)NN * 32;
    float* z = out + (size_t)2 * NN * 32;

    // ---- CSR build (reused by all 3 layers) ----
    deg_init<<<(NN + 255) / 256, 256>>>();
    deg_hist<<<(EE + 255) / 256, 256>>>(ei);
    scan_kernel<<<1, 1024>>>();
    scatter_kernel<<<(EE + NN + 255) / 256, 256>>>(ei);

    int agg_blocks = (NN + 7) / 8;  // one warp per node, 8 warps/block
    int gemm_rows = (NN + 127) / 128;

    // ---- layer 1: 128 -> 4x64 ----
    mm_tf32<<<dim3(4, gemm_rows), 256>>>(x, 0, W1, as1, ad1, NN, 128, 256, 64, 4);
    gat_aggregate<4, 64, true><<<agg_blocks, 256>>>(b1, nullptr, 1);

    // ---- layer 2: 64 -> 4x64 ----
    mm_tf32<<<dim3(4, gemm_rows), 256>>>(nullptr, 1, W2, as2, ad2, NN, 64, 256, 64, 4);
    gat_aggregate<4, 64, true><<<agg_blocks, 256>>>(b2, nullptr, 2);

    // ---- layer 3: 64 -> 1x32 ----
    mm_tf32<<<dim3(1, gemm_rows), 256>>>(nullptr, 2, W3, as3, ad3, NN, 64, 32, 32, 1);
    gat_aggregate<1, 32, false><<<agg_blocks, 256>>>(b3, z, 0);

    // ---- epilogue ----
    epilogue<<<agg_blocks, 256>>>(z, Wm, bm, Wv, bv, zmean, zvar);
}

// round 13
// speedup vs baseline: 1.5823x; 1.2025x over previous
#include <cuda_runtime.h>
#include <cuda_fp16.h>
#include <cuda_bf16.h>

#define NN 20000
#define EE 320000
#define IN_C 128
#define HID 64
#define OUT_C 32
#define NEG_SLOPE 0.2f

// ---------------- scratch (device globals; no allocation) ----------------
__device__ __align__(16) __half g_hh[NN * 256]; // GEMM output h in fp16 (max H*C = 256)
__device__ __align__(16) float g_f1[NN * 64];   // layer-1 node features (fp32)
__device__ __align__(16) float g_f2[NN * 64];   // layer-2 node features (fp32)
__device__ __align__(16) float g_as[NN * 4];    // alpha_src per node (max 4 heads)
__device__ __align__(16) float g_ad[NN * 4];    // alpha_dst per node
__device__ int   g_deg[NN];
__device__ int   g_rowptr[NN + 1];
__device__ int   g_cursor[NN];
__device__ int   g_part[32];
__device__ int   g_col[EE + NN];                // CSR: src per incoming edge (incl. self loops)

// buffer selector: 0 = external pointer, 1 = g_f1, 2 = g_f2
__device__ __forceinline__ float* sel_buf(int sel, float* ext) {
    if (sel == 1) return g_f1;
    if (sel == 2) return g_f2;
    return ext;
}
__device__ __forceinline__ const float* sel_cbuf(int sel, const float* ext) {
    if (sel == 1) return g_f1;
    if (sel == 2) return g_f2;
    return ext;
}

// ---------------- CSR build ----------------
__global__ void deg_init() {
    int i = blockIdx.x * blockDim.x + threadIdx.x;
    if (i < NN) g_deg[i] = 1;  // self loop
}

__global__ void deg_hist(const int* __restrict__ ei) {
    int e = blockIdx.x * blockDim.x + threadIdx.x;
    if (e < EE) {
        int d = ei[EE + e];
        atomicAdd(&g_deg[d], 1);
    }
}

// 3-phase scan over g_deg -> g_rowptr (inclusive at i+1), g_cursor (exclusive)
__global__ void scanA() {
    __shared__ int warpsum[32];
    int tid = threadIdx.x, lane = tid & 31, wid = tid >> 5;
    int i = blockIdx.x * 1024 + tid;
    int v = (i < NN) ? g_deg[i] : 0;
    int x = v;
#pragma unroll
    for (int off = 1; off < 32; off <<= 1) {
        int t = __shfl_up_sync(0xffffffffu, x, off);
        if (lane >= off) x += t;
    }
    if (lane == 31) warpsum[wid] = x;
    __syncthreads();
    if (wid == 0) {
        int w = warpsum[lane];
#pragma unroll
        for (int off = 1; off < 32; off <<= 1) {
            int t = __shfl_up_sync(0xffffffffu, w, off);
            if (lane >= off) w += t;
        }
        warpsum[lane] = w;
    }
    __syncthreads();
    int prefix = (wid > 0 ? warpsum[wid - 1] : 0);
    int incl = prefix + x;
    if (i < NN) { g_rowptr[i + 1] = incl; g_cursor[i] = incl - v; }
    if (tid == 1023) g_part[blockIdx.x] = incl;
}

__global__ void scanB(int nblk) {
    int lane = threadIdx.x;
    int v = (lane < nblk) ? g_part[lane] : 0;
    int x = v;
#pragma unroll
    for (int off = 1; off < 32; off <<= 1) {
        int t = __shfl_up_sync(0xffffffffu, x, off);
        if (lane >= off) x += t;
    }
    if (lane < nblk) g_part[lane] = x - v;  // exclusive
}

__global__ void scanC() {
    int tid = threadIdx.x;
    int i = blockIdx.x * 1024 + tid;
    int off = g_part[blockIdx.x];
    if (i < NN) { g_rowptr[i + 1] += off; g_cursor[i] += off; }
    if (i == 0) g_rowptr[0] = 0;
}

__global__ void scatter_kernel(const int* __restrict__ ei) {
    int id = blockIdx.x * blockDim.x + threadIdx.x;
    if (id >= EE + NN) return;
    int s, d;
    if (id < EE) { s = ei[id]; d = ei[EE + id]; }
    else { s = d = id - EE; }
    int pos = atomicAdd(&g_cursor[d], 1);
    g_col[pos] = s;
}

// ---------------- tf32 tensor-core GEMM + fused alpha ----------------
__device__ __forceinline__ unsigned f2tf32(float x) {
    unsigned r;
    asm("cvt.rna.tf32.f32 %0, %1;" : "=r"(r) : "f"(x));
    return r;
}

__device__ __forceinline__ void mma_tf32(float& c0, float& c1, float& c2, float& c3,
                                         unsigned a0, unsigned a1, unsigned a2, unsigned a3,
                                         unsigned b0, unsigned b1) {
    asm volatile(
        "mma.sync.aligned.m16n8k8.row.col.f32.tf32.tf32.f32 "
        "{%0,%1,%2,%3},{%4,%5,%6,%7},{%8,%9},{%0,%1,%2,%3};"
        : "+f"(c0), "+f"(c1), "+f"(c2), "+f"(c3)
        : "r"(a0), "r"(a1), "r"(a2), "r"(a3), "r"(b0), "r"(b1));
}

// Block tile 128(M) x 64(N) x 32(K); 256 threads = 8 warps in 4(M) x 2(N) grid.
__global__ void mm_tf32(const float* __restrict__ Aext, int Asel,
                        const float* __restrict__ B,
                        const float* __restrict__ avs, const float* __restrict__ avd,
                        int Nr, int K, int M, int Cc, int H) {
    const float* A = sel_cbuf(Asel, Aext);
    __shared__ unsigned As[128 * 36];
    __shared__ unsigned Bs[32 * 72];
    __shared__ float sAv[64], sDv[64];
    int tid = threadIdx.x;
    int lane = tid & 31;
    int w = tid >> 5;
    int wm = w & 3;
    int wn = w >> 2;
    int g = lane >> 2;
    int t = lane & 3;
    int row0 = blockIdx.y * 128;
    int col0 = blockIdx.x * 64;
    int head = blockIdx.x;

    if (tid < 64) sAv[tid] = (tid < Cc) ? avs[head * Cc + tid] : 0.f;
    else if (tid < 128) sDv[tid - 64] = (tid - 64 < Cc) ? avd[head * Cc + (tid - 64)] : 0.f;

    float acc[2][4][4];
#pragma unroll
    for (int mi = 0; mi < 2; mi++)
#pragma unroll
        for (int ni = 0; ni < 4; ni++)
#pragma unroll
            for (int q = 0; q < 4; q++) acc[mi][ni][q] = 0.f;

    for (int kt = 0; kt < K; kt += 32) {
#pragma unroll
        for (int i = 0; i < 4; i++) {
            int lin = tid + i * 256;
            int r = lin >> 3;
            int c4 = (lin & 7) * 4;
            float4 v = make_float4(0.f, 0.f, 0.f, 0.f);
            if (row0 + r < Nr)
                v = *(const float4*)(A + (size_t)(row0 + r) * K + kt + c4);
            uint4 u = make_uint4(f2tf32(v.x), f2tf32(v.y), f2tf32(v.z), f2tf32(v.w));
            *(uint4*)&As[r * 36 + c4] = u;
        }
#pragma unroll
        for (int i = 0; i < 2; i++) {
            int lin = tid + i * 256;
            int kk = lin >> 4;
            int c4 = (lin & 15) * 4;
            float4 v = make_float4(0.f, 0.f, 0.f, 0.f);
            if (col0 + c4 + 4 <= M) {
                v = *(const float4*)(B + (size_t)(kt + kk) * M + col0 + c4);
            } else if (col0 + c4 < M) {
                const float* br = B + (size_t)(kt + kk) * M;
                v.x = br[col0 + c4];
                if (col0 + c4 + 1 < M) v.y = br[col0 + c4 + 1];
                if (col0 + c4 + 2 < M) v.z = br[col0 + c4 + 2];
            }
            uint4 u = make_uint4(f2tf32(v.x), f2tf32(v.y), f2tf32(v.z), f2tf32(v.w));
            *(uint4*)&Bs[kk * 72 + c4] = u;
        }
        __syncthreads();

#pragma unroll
        for (int kk = 0; kk < 32; kk += 8) {
            unsigned a[2][4], b[4][2];
#pragma unroll
            for (int mi = 0; mi < 2; mi++) {
                int rowA = wm * 32 + mi * 16 + g;
                a[mi][0] = As[rowA * 36 + kk + t];
                a[mi][1] = As[(rowA + 8) * 36 + kk + t];
                a[mi][2] = As[rowA * 36 + kk + t + 4];
                a[mi][3] = As[(rowA + 8) * 36 + kk + t + 4];
            }
#pragma unroll
            for (int ni = 0; ni < 4; ni++) {
                int colB = wn * 32 + ni * 8 + g;
                b[ni][0] = Bs[(kk + t) * 72 + colB];
                b[ni][1] = Bs[(kk + t + 4) * 72 + colB];
            }
#pragma unroll
            for (int mi = 0; mi < 2; mi++)
#pragma unroll
                for (int ni = 0; ni < 4; ni++)
                    mma_tf32(acc[mi][ni][0], acc[mi][ni][1], acc[mi][ni][2], acc[mi][ni][3],
                             a[mi][0], a[mi][1], a[mi][2], a[mi][3], b[ni][0], b[ni][1]);
        }
        __syncthreads();
    }

    // store h as fp16
#pragma unroll
    for (int mi = 0; mi < 2; mi++) {
#pragma unroll
        for (int ni = 0; ni < 4; ni++) {
            int r = row0 + wm * 32 + mi * 16 + g;
            int c = col0 + wn * 32 + ni * 8 + 2 * t;
            if (r < Nr && c < M)
                *(half2*)&g_hh[(size_t)r * M + c] = __floats2half2_rn(acc[mi][ni][0], acc[mi][ni][1]);
            if (r + 8 < Nr && c < M)
                *(half2*)&g_hh[(size_t)(r + 8) * M + c] = __floats2half2_rn(acc[mi][ni][2], acc[mi][ni][3]);
        }
    }

    // fused alpha
    float rp_s[4] = {0.f, 0.f, 0.f, 0.f};
    float rp_d[4] = {0.f, 0.f, 0.f, 0.f};
#pragma unroll
    for (int mi = 0; mi < 2; mi++)
#pragma unroll
        for (int ni = 0; ni < 4; ni++) {
            int cl = wn * 32 + ni * 8 + 2 * t;
            float a0 = sAv[cl], a1 = sAv[cl + 1];
            float d0 = sDv[cl], d1 = sDv[cl + 1];
#pragma unroll
            for (int half = 0; half < 2; half++) {
                float x0 = acc[mi][ni][2 * half];
                float x1 = acc[mi][ni][2 * half + 1];
                rp_s[mi * 2 + half] += x0 * a0 + x1 * a1;
                rp_d[mi * 2 + half] += x0 * d0 + x1 * d1;
            }
        }
#pragma unroll
    for (int i = 0; i < 4; i++) {
#pragma unroll
        for (int off = 1; off <= 2; off <<= 1) {
            rp_s[i] += __shfl_xor_sync(0xffffffffu, rp_s[i], off);
            rp_d[i] += __shfl_xor_sync(0xffffffffu, rp_d[i], off);
        }
    }
    float* red = (float*)As;
    if (tid < 256) red[tid] = 0.f;
    __syncthreads();
    if (t == 0) {
#pragma unroll
        for (int mi = 0; mi < 2; mi++)
#pragma unroll
            for (int half = 0; half < 2; half++) {
                int rowl = wm * 32 + mi * 16 + half * 8 + g;
                atomicAdd(&red[rowl], rp_s[mi * 2 + half]);
                atomicAdd(&red[128 + rowl], rp_d[mi * 2 + half]);
            }
    }
    __syncthreads();
    if (tid < 128) {
        int r = row0 + tid;
        if (r < Nr) {
            g_as[(size_t)r * H + head] = red[tid];
            g_ad[(size_t)r * H + head] = red[128 + tid];
        }
    }
}

__device__ __forceinline__ float leaky(float x) { return x > 0.f ? x : NEG_SLOPE * x; }

// ---------------- GAT aggregate, H=4 C=64: one warp per node ----------------
// lane L owns flat channels 8L..8L+7 (head L/8); one LDG.128 per lane per edge.
template <bool RELU>
__global__ void gat_aggregate4(const float* __restrict__ bias, float* __restrict__ out_ext,
                               int out_sel) {
    float* out = sel_buf(out_sel, out_ext);
    __shared__ float p_s[8][32][4];
    int tid = threadIdx.x;
    int warp = (blockIdx.x * blockDim.x + tid) >> 5;
    int wloc = (tid >> 5) & 7;
    int lane = tid & 31;
    if (warp >= NN) return;
    int n = warp;
    int beg = g_rowptr[n], end = g_rowptr[n + 1];
    int hsel = lane >> 3;   // head of this lane

    float4 adv = ((const float4*)g_ad)[n];
    float ad[4] = {adv.x, adv.y, adv.z, adv.w};

    // pass 1: per-head max
    float m[4] = {-1e30f, -1e30f, -1e30f, -1e30f};
    for (int j = beg + lane; j < end; j += 32) {
        int s = g_col[j];
        float4 a = ((const float4*)g_as)[s];
        m[0] = fmaxf(m[0], leaky(a.x + ad[0]));
        m[1] = fmaxf(m[1], leaky(a.y + ad[1]));
        m[2] = fmaxf(m[2], leaky(a.z + ad[2]));
        m[3] = fmaxf(m[3], leaky(a.w + ad[3]));
    }
#pragma unroll
    for (int hh = 0; hh < 4; hh++)
#pragma unroll
        for (int off = 16; off > 0; off >>= 1)
            m[hh] = fmaxf(m[hh], __shfl_xor_sync(0xffffffffu, m[hh], off));

    // pass 2
    float2 acc[4];
#pragma unroll
    for (int k = 0; k < 4; k++) acc[k] = make_float2(0.f, 0.f);
    float ssum[4] = {0.f, 0.f, 0.f, 0.f};
    const uint4* hb = (const uint4*)g_hh;   // 16B granules; row = 32 granules

    for (int base = beg; base < end; base += 32) {
        int cnt = min(32, end - base);
        int sj = 0;
        if (lane < cnt) {
            sj = g_col[base + lane];
            float4 a = ((const float4*)g_as)[sj];
            float p0 = __expf(leaky(a.x + ad[0]) - m[0]);
            float p1 = __expf(leaky(a.y + ad[1]) - m[1]);
            float p2 = __expf(leaky(a.z + ad[2]) - m[2]);
            float p3 = __expf(leaky(a.w + ad[3]) - m[3]);
            ssum[0] += p0; ssum[1] += p1; ssum[2] += p2; ssum[3] += p3;
            *(float4*)&p_s[wloc][lane][0] = make_float4(p0, p1, p2, p3);
        }
        __syncwarp();

        int t = 0;
        for (; t + 4 <= cnt; t += 4) {
            int s0 = __shfl_sync(0xffffffffu, sj, t);
            int s1 = __shfl_sync(0xffffffffu, sj, t + 1);
            int s2 = __shfl_sync(0xffffffffu, sj, t + 2);
            int s3 = __shfl_sync(0xffffffffu, sj, t + 3);
            uint4 v0 = hb[(size_t)s0 * 32 + lane];
            uint4 v1 = hb[(size_t)s1 * 32 + lane];
            uint4 v2 = hb[(size_t)s2 * 32 + lane];
            uint4 v3 = hb[(size_t)s3 * 32 + lane];
            float q0 = p_s[wloc][t][hsel];
            float q1 = p_s[wloc][t + 1][hsel];
            float q2 = p_s[wloc][t + 2][hsel];
            float q3 = p_s[wloc][t + 3][hsel];
#define CONSUME(V, Q)                                                    \
            {                                                            \
                float2 f0 = __half22float2(*(const __half2*)&(V).x);     \
                float2 f1 = __half22float2(*(const __half2*)&(V).y);     \
                float2 f2 = __half22float2(*(const __half2*)&(V).z);     \
                float2 f3 = __half22float2(*(const __half2*)&(V).w);     \
                acc[0].x = fmaf(Q, f0.x, acc[0].x);                      \
                acc[0].y = fmaf(Q, f0.y, acc[0].y);                      \
                acc[1].x = fmaf(Q, f1.x, acc[1].x);                      \
                acc[1].y = fmaf(Q, f1.y, acc[1].y);                      \
                acc[2].x = fmaf(Q, f2.x, acc[2].x);                      \
                acc[2].y = fmaf(Q, f2.y, acc[2].y);                      \
                acc[3].x = fmaf(Q, f3.x, acc[3].x);                      \
                acc[3].y = fmaf(Q, f3.y, acc[3].y);                      \
            }
            CONSUME(v0, q0) CONSUME(v1, q1) CONSUME(v2, q2) CONSUME(v3, q3)
        }
        for (; t < cnt; t++) {
            int s0 = __shfl_sync(0xffffffffu, sj, t);
            uint4 v0 = hb[(size_t)s0 * 32 + lane];
            float q0 = p_s[wloc][t][hsel];
            CONSUME(v0, q0)
        }
#undef CONSUME
        __syncwarp();
    }

#pragma unroll
    for (int hh = 0; hh < 4; hh++)
#pragma unroll
        for (int off = 16; off > 0; off >>= 1)
            ssum[hh] += __shfl_xor_sync(0xffffffffu, ssum[hh], off);

    // per-lane inverse sum for its head
    float s01 = (lane & 8) ? ssum[1] : ssum[0];
    float s23 = (lane & 8) ? ssum[3] : ssum[2];
    float shead = (lane & 16) ? s23 : s01;
    float myinv = 1.f / (shead + 1e-16f);

    float vals[8];
#pragma unroll
    for (int k = 0; k < 4; k++) { vals[2 * k] = acc[k].x * myinv; vals[2 * k + 1] = acc[k].y * myinv; }
    // butterfly over head lanes (xor 8, 16) to sum heads
#pragma unroll
    for (int j = 0; j < 8; j++) {
        vals[j] += __shfl_xor_sync(0xffffffffu, vals[j], 8);
        vals[j] += __shfl_xor_sync(0xffffffffu, vals[j], 16);
    }
    if (lane < 8) {
        int c = 8 * lane;  // channel within head (C=64)
        float4 o0, o1;
        o0.x = vals[0] * 0.25f + bias[c + 0];
        o0.y = vals[1] * 0.25f + bias[c + 1];
        o0.z = vals[2] * 0.25f + bias[c + 2];
        o0.w = vals[3] * 0.25f + bias[c + 3];
        o1.x = vals[4] * 0.25f + bias[c + 4];
        o1.y = vals[5] * 0.25f + bias[c + 5];
        o1.z = vals[6] * 0.25f + bias[c + 6];
        o1.w = vals[7] * 0.25f + bias[c + 7];
        if (RELU) {
            o0.x = fmaxf(o0.x, 0.f); o0.y = fmaxf(o0.y, 0.f);
            o0.z = fmaxf(o0.z, 0.f); o0.w = fmaxf(o0.w, 0.f);
            o1.x = fmaxf(o1.x, 0.f); o1.y = fmaxf(o1.y, 0.f);
            o1.z = fmaxf(o1.z, 0.f); o1.w = fmaxf(o1.w, 0.f);
        }
        *(float4*)&out[(size_t)n * 64 + c] = o0;
        *(float4*)&out[(size_t)n * 64 + c + 4] = o1;
    }
}

// ---------------- GAT aggregate, H=1 C=32 (layer 3) ----------------
__global__ void gat_aggregate1(const float* __restrict__ bias, float* __restrict__ out) {
    int warp = (blockIdx.x * blockDim.x + threadIdx.x) >> 5;
    int lane = threadIdx.x & 31;
    if (warp >= NN) return;
    int n = warp;
    int beg = g_rowptr[n], end = g_rowptr[n + 1];
    float ad0 = g_ad[n];

    float m0 = -1e30f;
    for (int j = beg + lane; j < end; j += 32)
        m0 = fmaxf(m0, leaky(g_as[g_col[j]] + ad0));
#pragma unroll
    for (int off = 16; off > 0; off >>= 1)
        m0 = fmaxf(m0, __shfl_xor_sync(0xffffffffu, m0, off));

    float2 acc = make_float2(0.f, 0.f);
    float ssum = 0.f;
    const __half2* hb = (const __half2*)g_hh;   // row = 16 half2

    for (int base = beg; base < end; base += 32) {
        int cnt = min(32, end - base);
        int sj = 0;
        float p0 = 0.f;
        if (lane < cnt) {
            sj = g_col[base + lane];
            p0 = __expf(leaky(g_as[sj] + ad0) - m0);
            ssum += p0;
        }
        for (int t = 0; t < cnt; ++t) {
            int src = __shfl_sync(0xffffffffu, sj, t);
            float pb = __shfl_sync(0xffffffffu, p0, t);
            if (lane < 16) {
                float2 f = __half22float2(hb[(size_t)src * 16 + lane]);
                acc.x = fmaf(pb, f.x, acc.x);
                acc.y = fmaf(pb, f.y, acc.y);
            }
        }
    }
#pragma unroll
    for (int off = 16; off > 0; off >>= 1)
        ssum += __shfl_xor_sync(0xffffffffu, ssum, off);
    float inv = 1.f / (ssum + 1e-16f);
    if (lane < 16) {
        int c = 2 * lane;
        float vx = acc.x * inv + bias[c];
        float vy = acc.y * inv + bias[c + 1];
        *(float2*)&out[(size_t)n * 32 + c] = make_float2(vx, vy);
    }
}

// ---------------- epilogue: z_mean, z_var ----------------
__global__ void epilogue(const float* __restrict__ z, const float* __restrict__ Wm,
                         const float* __restrict__ bm, const float* __restrict__ Wv,
                         const float* __restrict__ bv, float* __restrict__ outm,
                         float* __restrict__ outv) {
    __shared__ float sWm[1024], sWv[1024], sbm[32], sbv[32];
    int tid = threadIdx.x;
    for (int i = tid; i < 1024; i += blockDim.x) { sWm[i] = Wm[i]; sWv[i] = Wv[i]; }
    if (tid < 32) { sbm[tid] = bm[tid]; sbv[tid] = bv[tid]; }
    __syncthreads();
    int warp = (blockIdx.x * blockDim.x + tid) >> 5;
    int lane = tid & 31;
    if (warp >= NN) return;
    float zc = z[(size_t)warp * 32 + lane];
    float am = 0.f, av = 0.f;
#pragma unroll
    for (int k = 0; k < 32; k++) {
        float zk = __shfl_sync(0xffffffffu, zc, k);
        am = fmaf(zk, sWm[k * 32 + lane], am);
        av = fmaf(zk, sWv[k * 32 + lane], av);
    }
    outm[(size_t)warp * 32 + lane] = am + sbm[lane];
    float v = __expf(av + sbv[lane]);
    outv[(size_t)warp * 32 + lane] = fminf(fmaxf(v, 1e-8f), 100.0f);
}

// ---------------- host launch ----------------
extern "C" void kernel_launch(void* const* d_in, const int* in_sizes, int n_in,
                              void* d_out, int out_size) {
    const float* x = (const float*)d_in[0];
    const int* ei = (const int*)d_in[1];
    const float* W1 = (const float*)d_in[2];
    const float* as1 = (const float*)d_in[3];
    const float* ad1 = (const float*)d_in[4];
    const float* b1 = (const float*)d_in[5];
    const float* W2 = (const float*)d_in[6];
    const float* as2 = (const float*)d_in[7];
    const float* ad2 = (const float*)d_in[8];
    const float* b2 = (const float*)d_in[9];
    const float* W3 = (const float*)d_in[10];
    const float* as3 = (const float*)d_in[11];
    const float* ad3 = (const float*)d_in[12];
    const float* b3 = (const float*)d_in[13];
    const float* Wm = (const float*)d_in[14];
    const float* bm = (const float*)d_in[15];
    const float* Wv = (const float*)d_in[16];
    const float* bv = (const float*)d_in[17];

    float* out = (float*)d_out;
    float* zmean = out;
    float* zvar = out + (size_t)NN * 32;
    float* z = out + (size_t)2 * NN * 32;

    int scan_blocks = (NN + 1023) / 1024;   // 20

    // ---- CSR build (reused by all 3 layers) ----
    deg_init<<<(NN + 255) / 256, 256>>>();
    deg_hist<<<(EE + 255) / 256, 256>>>(ei);
    scanA<<<scan_blocks, 1024>>>();
    scanB<<<1, 32>>>(scan_blocks);
    scanC<<<scan_blocks, 1024>>>();
    scatter_kernel<<<(EE + NN + 255) / 256, 256>>>(ei);

    int agg_blocks = (NN + 7) / 8;
    int gemm_rows = (NN + 127) / 128;

    // ---- layer 1: 128 -> 4x64 ----
    mm_tf32<<<dim3(4, gemm_rows), 256>>>(x, 0, W1, as1, ad1, NN, 128, 256, 64, 4);
    gat_aggregate4<true><<<agg_blocks, 256>>>(b1, nullptr, 1);

    // ---- layer 2: 64 -> 4x64 ----
    mm_tf32<<<dim3(4, gemm_rows), 256>>>(nullptr, 1, W2, as2, ad2, NN, 64, 256, 64, 4);
    gat_aggregate4<true><<<agg_blocks, 256>>>(b2, nullptr, 2);

    // ---- layer 3: 64 -> 1x32 ----
    mm_tf32<<<dim3(1, gemm_rows), 256>>>(nullptr, 2, W3, as3, ad3, NN, 64, 32, 32, 1);
    gat_aggregate1<<<agg_blocks, 256>>>(b3, z);

    // ---- epilogue ----
    epilogue<<<agg_blocks, 256>>>(z, Wm, bm, Wv, bv, zmean, zvar);
}

// round 15
// speedup vs baseline: 1.6197x; 1.0237x over previous
#include <cuda_runtime.h>
#include <cuda_fp16.h>
#include <cuda_bf16.h>

#define NN 20000
#define EE 320000
#define IN_C 128
#define HID 64
#define OUT_C 32
#define NEG_SLOPE 0.2f

// ---------------- scratch (device globals; no allocation) ----------------
__device__ __align__(16) __half g_hh[NN * 256]; // GEMM output h in fp16 (max H*C = 256)
__device__ __align__(16) float g_f1[NN * 64];   // layer-1 node features (fp32)
__device__ __align__(16) float g_f2[NN * 64];   // layer-2 node features (fp32)
__device__ __align__(16) float g_as[NN * 4];    // alpha_src per node (max 4 heads)
__device__ __align__(16) float g_ad[NN * 4];    // alpha_dst per node
__device__ int   g_deg[NN];                     // zero at module load; re-zeroed by epilogue
__device__ int   g_rowptr[NN + 1];
__device__ int   g_cursor[NN];
__device__ int   g_part[32];
__device__ int   g_col[EE + NN];                // CSR: src per incoming edge (incl. self loops)

// buffer selector: 0 = external pointer, 1 = g_f1, 2 = g_f2
__device__ __forceinline__ float* sel_buf(int sel, float* ext) {
    if (sel == 1) return g_f1;
    if (sel == 2) return g_f2;
    return ext;
}
__device__ __forceinline__ const float* sel_cbuf(int sel, const float* ext) {
    if (sel == 1) return g_f1;
    if (sel == 2) return g_f2;
    return ext;
}

// ---------------- CSR build ----------------
// 4 edges per thread -> 4 outstanding atomics (ATOMG lat ~318cyc, MLP=4)
__global__ void deg_hist4(const int* __restrict__ ei) {
    int t = blockIdx.x * blockDim.x + threadIdx.x;
    const int Q = EE / 4;
    if (t < Q) {
        int4 d4 = ((const int4*)(ei + EE))[t];
        atomicAdd(&g_deg[d4.x], 1);
        atomicAdd(&g_deg[d4.y], 1);
        atomicAdd(&g_deg[d4.z], 1);
        atomicAdd(&g_deg[d4.w], 1);
    }
}

// scanA: block-local inclusive scan of (deg[i]+1); writes rowptr/cursor (pre-offset), partial per block
__global__ void scanA() {
    __shared__ int warpsum[32];
    int tid = threadIdx.x, lane = tid & 31, wid = tid >> 5;
    int i = blockIdx.x * 1024 + tid;
    int v = (i < NN) ? (g_deg[i] + 1) : 0;   // +1 = self loop
    int x = v;
#pragma unroll
    for (int off = 1; off < 32; off <<= 1) {
        int t = __shfl_up_sync(0xffffffffu, x, off);
        if (lane >= off) x += t;
    }
    if (lane == 31) warpsum[wid] = x;
    __syncthreads();
    if (wid == 0) {
        int w = warpsum[lane];
#pragma unroll
        for (int off = 1; off < 32; off <<= 1) {
            int t = __shfl_up_sync(0xffffffffu, w, off);
            if (lane >= off) w += t;
        }
        warpsum[lane] = w;
    }
    __syncthreads();
    int prefix = (wid > 0 ? warpsum[wid - 1] : 0);
    int incl = prefix + x;
    if (i < NN) { g_rowptr[i + 1] = incl; g_cursor[i] = incl - v; }
    if (tid == 1023) g_part[blockIdx.x] = incl;
}

// scanC: each block redundantly scans the <=32 partials, applies its offset
__global__ void scanC(int nblk) {
    __shared__ int soff;
    int tid = threadIdx.x;
    if (tid < 32) {
        int v = (tid < nblk) ? g_part[tid] : 0;
        int x = v;
#pragma unroll
        for (int off = 1; off < 32; off <<= 1) {
            int t = __shfl_up_sync(0xffffffffu, x, off);
            if (tid >= off) x += t;
        }
        if (tid == blockIdx.x) soff = x - v;  // exclusive prefix for this block
    }
    __syncthreads();
    int i = blockIdx.x * 1024 + tid;
    int off = soff;
    if (i < NN) { g_rowptr[i + 1] += off; g_cursor[i] += off; }
    if (i == 0) g_rowptr[0] = 0;
}

// scatter: 4 edges per thread + self loops
__global__ void scatter4(const int* __restrict__ ei) {
    int t = blockIdx.x * blockDim.x + threadIdx.x;
    const int Q = EE / 4;
    if (t < Q) {
        int4 s4 = ((const int4*)ei)[t];
        int4 d4 = ((const int4*)(ei + EE))[t];
        int p0 = atomicAdd(&g_cursor[d4.x], 1);
        int p1 = atomicAdd(&g_cursor[d4.y], 1);
        int p2 = atomicAdd(&g_cursor[d4.z], 1);
        int p3 = atomicAdd(&g_cursor[d4.w], 1);
        g_col[p0] = s4.x;
        g_col[p1] = s4.y;
        g_col[p2] = s4.z;
        g_col[p3] = s4.w;
    } else if (t < Q + NN) {
        int n = t - Q;
        int p = atomicAdd(&g_cursor[n], 1);
        g_col[p] = n;
    }
}

// ---------------- tf32 tensor-core GEMM + fused alpha ----------------
__device__ __forceinline__ unsigned f2tf32(float x) {
    unsigned r;
    asm("cvt.rna.tf32.f32 %0, %1;" : "=r"(r) : "f"(x));
    return r;
}

__device__ __forceinline__ void mma_tf32(float& c0, float& c1, float& c2, float& c3,
                                         unsigned a0, unsigned a1, unsigned a2, unsigned a3,
                                         unsigned b0, unsigned b1) {
    asm volatile(
        "mma.sync.aligned.m16n8k8.row.col.f32.tf32.tf32.f32 "
        "{%0,%1,%2,%3},{%4,%5,%6,%7},{%8,%9},{%0,%1,%2,%3};"
        : "+f"(c0), "+f"(c1), "+f"(c2), "+f"(c3)
        : "r"(a0), "r"(a1), "r"(a2), "r"(a3), "r"(b0), "r"(b1));
}

// Block tile 128(M) x 64(N) x 32(K); 256 threads = 8 warps in 4(M) x 2(N) grid.
__global__ void mm_tf32(const float* __restrict__ Aext, int Asel,
                        const float* __restrict__ B,
                        const float* __restrict__ avs, const float* __restrict__ avd,
                        int Nr, int K, int M, int Cc, int H) {
    const float* A = sel_cbuf(Asel, Aext);
    __shared__ unsigned As[128 * 36];
    __shared__ unsigned Bs[32 * 72];
    __shared__ float sAv[64], sDv[64];
    int tid = threadIdx.x;
    int lane = tid & 31;
    int w = tid >> 5;
    int wm = w & 3;
    int wn = w >> 2;
    int g = lane >> 2;
    int t = lane & 3;
    int row0 = blockIdx.y * 128;
    int col0 = blockIdx.x * 64;
    int head = blockIdx.x;

    if (tid < 64) sAv[tid] = (tid < Cc) ? avs[head * Cc + tid] : 0.f;
    else if (tid < 128) sDv[tid - 64] = (tid - 64 < Cc) ? avd[head * Cc + (tid - 64)] : 0.f;

    float acc[2][4][4];
#pragma unroll
    for (int mi = 0; mi < 2; mi++)
#pragma unroll
        for (int ni = 0; ni < 4; ni++)
#pragma unroll
            for (int q = 0; q < 4; q++) acc[mi][ni][q] = 0.f;

    for (int kt = 0; kt < K; kt += 32) {
#pragma unroll
        for (int i = 0; i < 4; i++) {
            int lin = tid + i * 256;
            int r = lin >> 3;
            int c4 = (lin & 7) * 4;
            float4 v = make_float4(0.f, 0.f, 0.f, 0.f);
            if (row0 + r < Nr)
                v = *(const float4*)(A + (size_t)(row0 + r) * K + kt + c4);
            uint4 u = make_uint4(f2tf32(v.x), f2tf32(v.y), f2tf32(v.z), f2tf32(v.w));
            *(uint4*)&As[r * 36 + c4] = u;
        }
#pragma unroll
        for (int i = 0; i < 2; i++) {
            int lin = tid + i * 256;
            int kk = lin >> 4;
            int c4 = (lin & 15) * 4;
            float4 v = make_float4(0.f, 0.f, 0.f, 0.f);
            if (col0 + c4 + 4 <= M) {
                v = *(const float4*)(B + (size_t)(kt + kk) * M + col0 + c4);
            } else if (col0 + c4 < M) {
                const float* br = B + (size_t)(kt + kk) * M;
                v.x = br[col0 + c4];
                if (col0 + c4 + 1 < M) v.y = br[col0 + c4 + 1];
                if (col0 + c4 + 2 < M) v.z = br[col0 + c4 + 2];
            }
            uint4 u = make_uint4(f2tf32(v.x), f2tf32(v.y), f2tf32(v.z), f2tf32(v.w));
            *(uint4*)&Bs[kk * 72 + c4] = u;
        }
        __syncthreads();

#pragma unroll
        for (int kk = 0; kk < 32; kk += 8) {
            unsigned a[2][4], b[4][2];
#pragma unroll
            for (int mi = 0; mi < 2; mi++) {
                int rowA = wm * 32 + mi * 16 + g;
                a[mi][0] = As[rowA * 36 + kk + t];
                a[mi][1] = As[(rowA + 8) * 36 + kk + t];
                a[mi][2] = As[rowA * 36 + kk + t + 4];
                a[mi][3] = As[(rowA + 8) * 36 + kk + t + 4];
            }
#pragma unroll
            for (int ni = 0; ni < 4; ni++) {
                int colB = wn * 32 + ni * 8 + g;
                b[ni][0] = Bs[(kk + t) * 72 + colB];
                b[ni][1] = Bs[(kk + t + 4) * 72 + colB];
            }
#pragma unroll
            for (int mi = 0; mi < 2; mi++)
#pragma unroll
                for (int ni = 0; ni < 4; ni++)
                    mma_tf32(acc[mi][ni][0], acc[mi][ni][1], acc[mi][ni][2], acc[mi][ni][3],
                             a[mi][0], a[mi][1], a[mi][2], a[mi][3], b[ni][0], b[ni][1]);
        }
        __syncthreads();
    }

    // store h as fp16
#pragma unroll
    for (int mi = 0; mi < 2; mi++) {
#pragma unroll
        for (int ni = 0; ni < 4; ni++) {
            int r = row0 + wm * 32 + mi * 16 + g;
            int c = col0 + wn * 32 + ni * 8 + 2 * t;
            if (r < Nr && c < M)
                *(half2*)&g_hh[(size_t)r * M + c] = __floats2half2_rn(acc[mi][ni][0], acc[mi][ni][1]);
            if (r + 8 < Nr && c < M)
                *(half2*)&g_hh[(size_t)(r + 8) * M + c] = __floats2half2_rn(acc[mi][ni][2], acc[mi][ni][3]);
        }
    }

    // fused alpha
    float rp_s[4] = {0.f, 0.f, 0.f, 0.f};
    float rp_d[4] = {0.f, 0.f, 0.f, 0.f};
#pragma unroll
    for (int mi = 0; mi < 2; mi++)
#pragma unroll
        for (int ni = 0; ni < 4; ni++) {
            int cl = wn * 32 + ni * 8 + 2 * t;
            float a0 = sAv[cl], a1 = sAv[cl + 1];
            float d0 = sDv[cl], d1 = sDv[cl + 1];
#pragma unroll
            for (int half = 0; half < 2; half++) {
                float x0 = acc[mi][ni][2 * half];
                float x1 = acc[mi][ni][2 * half + 1];
                rp_s[mi * 2 + half] += x0 * a0 + x1 * a1;
                rp_d[mi * 2 + half] += x0 * d0 + x1 * d1;
            }
        }
#pragma unroll
    for (int i = 0; i < 4; i++) {
#pragma unroll
        for (int off = 1; off <= 2; off <<= 1) {
            rp_s[i] += __shfl_xor_sync(0xffffffffu, rp_s[i], off);
            rp_d[i] += __shfl_xor_sync(0xffffffffu, rp_d[i], off);
        }
    }
    float* red = (float*)As;
    if (tid < 256) red[tid] = 0.f;
    __syncthreads();
    if (t == 0) {
#pragma unroll
        for (int mi = 0; mi < 2; mi++)
#pragma unroll
            for (int half = 0; half < 2; half++) {
                int rowl = wm * 32 + mi * 16 + half * 8 + g;
                atomicAdd(&red[rowl], rp_s[mi * 2 + half]);
                atomicAdd(&red[128 + rowl], rp_d[mi * 2 + half]);
            }
    }
    __syncthreads();
    if (tid < 128) {
        int r = row0 + tid;
        if (r < Nr) {
            g_as[(size_t)r * H + head] = red[tid];
            g_ad[(size_t)r * H + head] = red[128 + tid];
        }
    }
}

__device__ __forceinline__ float leaky(float x) { return x > 0.f ? x : NEG_SLOPE * x; }

// ---------------- GAT aggregate, H=4 C=64: one warp per node ----------------
template <bool RELU>
__global__ void gat_aggregate4(const float* __restrict__ bias, float* __restrict__ out_ext,
                               int out_sel) {
    float* out = sel_buf(out_sel, out_ext);
    __shared__ float p_s[8][32][4];
    int tid = threadIdx.x;
    int warp = (blockIdx.x * blockDim.x + tid) >> 5;
    int wloc = (tid >> 5) & 7;
    int lane = tid & 31;
    if (warp >= NN) return;
    int n = warp;
    int beg = g_rowptr[n], end = g_rowptr[n + 1];
    int hsel = lane >> 3;

    float4 adv = ((const float4*)g_ad)[n];
    float ad[4] = {adv.x, adv.y, adv.z, adv.w};

    float m[4] = {-1e30f, -1e30f, -1e30f, -1e30f};
    for (int j = beg + lane; j < end; j += 32) {
        int s = g_col[j];
        float4 a = ((const float4*)g_as)[s];
        m[0] = fmaxf(m[0], leaky(a.x + ad[0]));
        m[1] = fmaxf(m[1], leaky(a.y + ad[1]));
        m[2] = fmaxf(m[2], leaky(a.z + ad[2]));
        m[3] = fmaxf(m[3], leaky(a.w + ad[3]));
    }
#pragma unroll
    for (int hh = 0; hh < 4; hh++)
#pragma unroll
        for (int off = 16; off > 0; off >>= 1)
            m[hh] = fmaxf(m[hh], __shfl_xor_sync(0xffffffffu, m[hh], off));

    float2 acc[4];
#pragma unroll
    for (int k = 0; k < 4; k++) acc[k] = make_float2(0.f, 0.f);
    float ssum[4] = {0.f, 0.f, 0.f, 0.f};
    const uint4* hb = (const uint4*)g_hh;

    for (int base = beg; base < end; base += 32) {
        int cnt = min(32, end - base);
        int sj = 0;
        if (lane < cnt) {
            sj = g_col[base + lane];
            float4 a = ((const float4*)g_as)[sj];
            float p0 = __expf(leaky(a.x + ad[0]) - m[0]);
            float p1 = __expf(leaky(a.y + ad[1]) - m[1]);
            float p2 = __expf(leaky(a.z + ad[2]) - m[2]);
            float p3 = __expf(leaky(a.w + ad[3]) - m[3]);
            ssum[0] += p0; ssum[1] += p1; ssum[2] += p2; ssum[3] += p3;
            *(float4*)&p_s[wloc][lane][0] = make_float4(p0, p1, p2, p3);
        }
        __syncwarp();

        int t = 0;
        for (; t + 4 <= cnt; t += 4) {
            int s0 = __shfl_sync(0xffffffffu, sj, t);
            int s1 = __shfl_sync(0xffffffffu, sj, t + 1);
            int s2 = __shfl_sync(0xffffffffu, sj, t + 2);
            int s3 = __shfl_sync(0xffffffffu, sj, t + 3);
            uint4 v0 = hb[(size_t)s0 * 32 + lane];
            uint4 v1 = hb[(size_t)s1 * 32 + lane];
            uint4 v2 = hb[(size_t)s2 * 32 + lane];
            uint4 v3 = hb[(size_t)s3 * 32 + lane];
            float q0 = p_s[wloc][t][hsel];
            float q1 = p_s[wloc][t + 1][hsel];
            float q2 = p_s[wloc][t + 2][hsel];
            float q3 = p_s[wloc][t + 3][hsel];
#define CONSUME(V, Q)                                                    \
            {                                                            \
                float2 f0 = __half22float2(*(const __half2*)&(V).x);     \
                float2 f1 = __half22float2(*(const __half2*)&(V).y);     \
                float2 f2 = __half22float2(*(const __half2*)&(V).z);     \
                float2 f3 = __half22float2(*(const __half2*)&(V).w);     \
                acc[0].x = fmaf(Q, f0.x, acc[0].x);                      \
                acc[0].y = fmaf(Q, f0.y, acc[0].y);                      \
                acc[1].x = fmaf(Q, f1.x, acc[1].x);                      \
                acc[1].y = fmaf(Q, f1.y, acc[1].y);                      \
                acc[2].x = fmaf(Q, f2.x, acc[2].x);                      \
                acc[2].y = fmaf(Q, f2.y, acc[2].y);                      \
                acc[3].x = fmaf(Q, f3.x, acc[3].x);                      \
                acc[3].y = fmaf(Q, f3.y, acc[3].y);                      \
            }
            CONSUME(v0, q0) CONSUME(v1, q1) CONSUME(v2, q2) CONSUME(v3, q3)
        }
        for (; t < cnt; t++) {
            int s0 = __shfl_sync(0xffffffffu, sj, t);
            uint4 v0 = hb[(size_t)s0 * 32 + lane];
            float q0 = p_s[wloc][t][hsel];
            CONSUME(v0, q0)
        }
#undef CONSUME
        __syncwarp();
    }

#pragma unroll
    for (int hh = 0; hh < 4; hh++)
#pragma unroll
        for (int off = 16; off > 0; off >>= 1)
            ssum[hh] += __shfl_xor_sync(0xffffffffu, ssum[hh], off);

    float s01 = (lane & 8) ? ssum[1] : ssum[0];
    float s23 = (lane & 8) ? ssum[3] : ssum[2];
    float shead = (lane & 16) ? s23 : s01;
    float myinv = 1.f / (shead + 1e-16f);

    float vals[8];
#pragma unroll
    for (int k = 0; k < 4; k++) { vals[2 * k] = acc[k].x * myinv; vals[2 * k + 1] = acc[k].y * myinv; }
#pragma unroll
    for (int j = 0; j < 8; j++) {
        vals[j] += __shfl_xor_sync(0xffffffffu, vals[j], 8);
        vals[j] += __shfl_xor_sync(0xffffffffu, vals[j], 16);
    }
    if (lane < 8) {
        int c = 8 * lane;
        float4 o0, o1;
        o0.x = vals[0] * 0.25f + bias[c + 0];
        o0.y = vals[1] * 0.25f + bias[c + 1];
        o0.z = vals[2] * 0.25f + bias[c + 2];
        o0.w = vals[3] * 0.25f + bias[c + 3];
        o1.x = vals[4] * 0.25f + bias[c + 4];
        o1.y = vals[5] * 0.25f + bias[c + 5];
        o1.z = vals[6] * 0.25f + bias[c + 6];
        o1.w = vals[7] * 0.25f + bias[c + 7];
        if (RELU) {
            o0.x = fmaxf(o0.x, 0.f); o0.y = fmaxf(o0.y, 0.f);
            o0.z = fmaxf(o0.z, 0.f); o0.w = fmaxf(o0.w, 0.f);
            o1.x = fmaxf(o1.x, 0.f); o1.y = fmaxf(o1.y, 0.f);
            o1.z = fmaxf(o1.z, 0.f); o1.w = fmaxf(o1.w, 0.f);
        }
        *(float4*)&out[(size_t)n * 64 + c] = o0;
        *(float4*)&out[(size_t)n * 64 + c + 4] = o1;
    }
}

// ---------------- GAT aggregate, H=1 C=32 (layer 3) ----------------
__global__ void gat_aggregate1(const float* __restrict__ bias, float* __restrict__ out) {
    int warp = (blockIdx.x * blockDim.x + threadIdx.x) >> 5;
    int lane = threadIdx.x & 31;
    if (warp >= NN) return;
    int n = warp;
    int beg = g_rowptr[n], end = g_rowptr[n + 1];
    float ad0 = g_ad[n];

    float m0 = -1e30f;
    for (int j = beg + lane; j < end; j += 32)
        m0 = fmaxf(m0, leaky(g_as[g_col[j]] + ad0));
#pragma unroll
    for (int off = 16; off > 0; off >>= 1)
        m0 = fmaxf(m0, __shfl_xor_sync(0xffffffffu, m0, off));

    float2 acc = make_float2(0.f, 0.f);
    float ssum = 0.f;
    const __half2* hb = (const __half2*)g_hh;

    for (int base = beg; base < end; base += 32) {
        int cnt = min(32, end - base);
        int sj = 0;
        float p0 = 0.f;
        if (lane < cnt) {
            sj = g_col[base + lane];
            p0 = __expf(leaky(g_as[sj] + ad0) - m0);
            ssum += p0;
        }
        for (int t = 0; t < cnt; ++t) {
            int src = __shfl_sync(0xffffffffu, sj, t);
            float pb = __shfl_sync(0xffffffffu, p0, t);
            if (lane < 16) {
                float2 f = __half22float2(hb[(size_t)src * 16 + lane]);
                acc.x = fmaf(pb, f.x, acc.x);
                acc.y = fmaf(pb, f.y, acc.y);
            }
        }
    }
#pragma unroll
    for (int off = 16; off > 0; off >>= 1)
        ssum += __shfl_xor_sync(0xffffffffu, ssum, off);
    float inv = 1.f / (ssum + 1e-16f);
    if (lane < 16) {
        int c = 2 * lane;
        float vx = acc.x * inv + bias[c];
        float vy = acc.y * inv + bias[c + 1];
        *(float2*)&out[(size_t)n * 32 + c] = make_float2(vx, vy);
    }
}

// ---------------- epilogue: z_mean, z_var; also re-zeros g_deg for next replay ----------------
__global__ void epilogue(const float* __restrict__ z, const float* __restrict__ Wm,
                         const float* __restrict__ bm, const float* __restrict__ Wv,
                         const float* __restrict__ bv, float* __restrict__ outm,
                         float* __restrict__ outv) {
    __shared__ float sWm[1024], sWv[1024], sbm[32], sbv[32];
    int tid = threadIdx.x;
    int gidx = blockIdx.x * blockDim.x + tid;
    if (gidx < NN) g_deg[gidx] = 0;  // reset for next graph replay
    for (int i = tid; i < 1024; i += blockDim.x) { sWm[i] = Wm[i]; sWv[i] = Wv[i]; }
    if (tid < 32) { sbm[tid] = bm[tid]; sbv[tid] = bv[tid]; }
    __syncthreads();
    int warp = gidx >> 5;
    int lane = tid & 31;
    if (warp >= NN) return;
    float zc = z[(size_t)warp * 32 + lane];
    float am = 0.f, av = 0.f;
#pragma unroll
    for (int k = 0; k < 32; k++) {
        float zk = __shfl_sync(0xffffffffu, zc, k);
        am = fmaf(zk, sWm[k * 32 + lane], am);
        av = fmaf(zk, sWv[k * 32 + lane], av);
    }
    outm[(size_t)warp * 32 + lane] = am + sbm[lane];
    float v = __expf(av + sbv[lane]);
    outv[(size_t)warp * 32 + lane] = fminf(fmaxf(v, 1e-8f), 100.0f);
}

// ---------------- host launch ----------------
extern "C" void kernel_launch(void* const* d_in, const int* in_sizes, int n_in,
                              void* d_out, int out_size) {
    const float* x = (const float*)d_in[0];
    const int* ei = (const int*)d_in[1];
    const float* W1 = (const float*)d_in[2];
    const float* as1 = (const float*)d_in[3];
    const float* ad1 = (const float*)d_in[4];
    const float* b1 = (const float*)d_in[5];
    const float* W2 = (const float*)d_in[6];
    const float* as2 = (const float*)d_in[7];
    const float* ad2 = (const float*)d_in[8];
    const float* b2 = (const float*)d_in[9];
    const float* W3 = (const float*)d_in[10];
    const float* as3 = (const float*)d_in[11];
    const float* ad3 = (const float*)d_in[12];
    const float* b3 = (const float*)d_in[13];
    const float* Wm = (const float*)d_in[14];
    const float* bm = (const float*)d_in[15];
    const float* Wv = (const float*)d_in[16];
    const float* bv = (const float*)d_in[17];

    float* out = (float*)d_out;
    float* zmean = out;
    float* zvar = out + (size_t)NN * 32;
    float* z = out + (size_t)2 * NN * 32;

    int scan_blocks = (NN + 1023) / 1024;   // 20
    const int Q = EE / 4;                   // 80000

    // ---- CSR build (reused by all 3 layers); g_deg starts zeroed, re-zeroed by epilogue ----
    deg_hist4<<<(Q + 255) / 256, 256>>>(ei);
    scanA<<<scan_blocks, 1024>>>();
    scanC<<<scan_blocks, 1024>>>(scan_blocks);
    scatter4<<<(Q + NN + 255) / 256, 256>>>(ei);

    int agg_blocks = (NN + 7) / 8;
    int gemm_rows = (NN + 127) / 128;

    // ---- layer 1: 128 -> 4x64 ----
    mm_tf32<<<dim3(4, gemm_rows), 256>>>(x, 0, W1, as1, ad1, NN, 128, 256, 64, 4);
    gat_aggregate4<true><<<agg_blocks, 256>>>(b1, nullptr, 1);

    // ---- layer 2: 64 -> 4x64 ----
    mm_tf32<<<dim3(4, gemm_rows), 256>>>(nullptr, 1, W2, as2, ad2, NN, 64, 256, 64, 4);
    gat_aggregate4<true><<<agg_blocks, 256>>>(b2, nullptr, 2);

    // ---- layer 3: 64 -> 1x32 ----
    mm_tf32<<<dim3(1, gemm_rows), 256>>>(nullptr, 2, W3, as3, ad3, NN, 64, 32, 32, 1);
    gat_aggregate1<<<agg_blocks, 256>>>(b3, z);

    // ---- epilogue (+ g_deg reset) ----
    epilogue<<<agg_blocks, 256>>>(z, Wm, bm, Wv, bv, zmean, zvar);
}